// round 13
// baseline (speedup 1.0000x reference)
#include <cuda_runtime.h>
#include <cuda_fp16.h>
#include <math.h>
#include <cstdint>

#define NB     32
#define SEQ    240
#define HID    1024
#define NLAYER 8
#define NHEAD  16
#define DHEAD  64
#define NVOCAB 48
#define BS_TOT (NB*SEQ)   // 7680
#define QKVW   3072

// ---------------- device scratch (no allocation allowed) ----------------
__device__ float  g_z   [BS_TOT*HID];
__device__ __half g_z16 [BS_TOT*HID];
__device__ __half g_qkv16[(long long)BS_TOT*QKVW];
__device__ __half g_att16[BS_TOT*HID];     // attention out & FFN out (fp16)
__device__ float  g_z1  [BS_TOT*HID];
__device__ __half g_z116[BS_TOT*HID];
__device__ __half g_ffh16[BS_TOT*HID];
__device__ float  g_pool[NB*HID];
__device__ __half g_wqkv16[(long long)NLAYER*3*HID*HID];  // [L][3072][1024] transposed fp16
__device__ __half g_w1216 [(long long)NLAYER*2*HID*HID];  // [L][W1t|W2t] fp16
__device__ float  g_bqkv[NLAYER*QKVW];

// ============================ helpers ============================
__device__ __forceinline__ uint32_t smem_u32(const void* p) {
    return (uint32_t)__cvta_generic_to_shared(p);
}
__device__ __forceinline__ void cpa16(uint32_t dst, const void* src) {
    asm volatile("cp.async.cg.shared.global [%0], [%1], 16;" :: "r"(dst), "l"(src));
}
#define CPA_COMMIT() asm volatile("cp.async.commit_group;" ::: "memory")
template<int N> __device__ __forceinline__ void cpa_wait() {
    asm volatile("cp.async.wait_group %0;" :: "n"(N) : "memory");
}

__device__ __forceinline__ void mma_f16(float* c, const uint32_t* a, uint32_t b0, uint32_t b1) {
    asm volatile(
        "mma.sync.aligned.m16n8k16.row.col.f32.f16.f16.f32 "
        "{%0,%1,%2,%3}, {%4,%5,%6,%7}, {%8,%9}, {%0,%1,%2,%3};"
        : "+f"(c[0]), "+f"(c[1]), "+f"(c[2]), "+f"(c[3])
        : "r"(a[0]), "r"(a[1]), "r"(a[2]), "r"(a[3]), "r"(b0), "r"(b1));
}
__device__ __forceinline__ void ldsm_x4(uint32_t* r, uint32_t addr) {
    asm volatile("ldmatrix.sync.aligned.m8n8.x4.shared.b16 {%0,%1,%2,%3}, [%4];"
        : "=r"(r[0]), "=r"(r[1]), "=r"(r[2]), "=r"(r[3]) : "r"(addr));
}
__device__ __forceinline__ void ldsm_x4_t(uint32_t* r, uint32_t addr) {
    asm volatile("ldmatrix.sync.aligned.m8n8.x4.trans.shared.b16 {%0,%1,%2,%3}, [%4];"
        : "=r"(r[0]), "=r"(r[1]), "=r"(r[2]), "=r"(r[3]) : "r"(addr));
}

// ============================ weight transpose -> fp16 ============================
__global__ void transpose_h_kernel(const float* __restrict__ src, __half* __restrict__ dst,
                                   long long dstZ) {
    __shared__ float t[32][33];
    long long smoff = (long long)blockIdx.z * HID * HID;
    long long dmoff = (long long)blockIdx.z * dstZ;
    int x0 = blockIdx.x * 32, y0 = blockIdx.y * 32;
    int tx = threadIdx.x, ty = threadIdx.y;  // 32 x 8
#pragma unroll
    for (int j = 0; j < 32; j += 8)
        t[ty + j][tx] = src[smoff + (long long)(y0 + ty + j) * HID + x0 + tx];
    __syncthreads();
#pragma unroll
    for (int j = 0; j < 32; j += 8)
        dst[dmoff + (long long)(x0 + ty + j) * HID + y0 + tx] = __float2half(t[tx][ty + j]);
}

// bias pack: g_bqkv[l][t*1024+n]
__global__ void biaspack_kernel(const float* __restrict__ bq, const float* __restrict__ bk,
                                const float* __restrict__ bv) {
    int idx = blockIdx.x * 256 + threadIdx.x;
    if (idx >= NLAYER * QKVW) return;
    int l = idx / QKVW, r = idx % QKVW;
    int t = r >> 10, n = r & 1023;
    const float* src = (t == 0) ? bq : (t == 1) ? bk : bv;
    g_bqkv[idx] = src[l * HID + n];
}

// ============================ fp16 mma.sync GEMM, 128x256 tile ============================
// C[M,N] = A[M,K] @ Wt^T + bias ; A fp16 [M,K] (lda=HID), Wt fp16 [N,K].
// BM=128, BN=256, BK=32 halves; 256 threads; warp grid 4(M)x2(N), warp tile 32x128.
#define BKC    32
#define PADH   40
#define A_BYTES (128 * PADH * 2)          // 10240
#define B_BYTES (256 * PADH * 2)          // 20480
#define STAGEB  (A_BYTES + B_BYTES)       // 30720
#define NSTAGE  3
#define GEMM_SMEM (NSTAGE * STAGEB)       // 92160

__device__ __forceinline__ void gemm_load_stage(uint32_t sbase, int s, int kc, int tid,
                                                const __half* __restrict__ A,
                                                const __half* __restrict__ Bw,
                                                int row0, int col0) {
    uint32_t abase = sbase + s * STAGEB;
    uint32_t bbase = abase + A_BYTES;
    const __half* Ag = A  + (long long)row0 * HID + kc * BKC;
    const __half* Bg = Bw + (long long)col0 * HID + kc * BKC;
#pragma unroll
    for (int j = 0; j < 6; j++) {
        int i = tid + j * 256;           // 0..1535
        if (i < 512) {
            int r = i >> 2, q = i & 3;
            uint32_t so = (uint32_t)(r * PADH + q * 8) * 2;
            cpa16(abase + so, Ag + (long long)r * HID + q * 8);
        } else {
            int k = i - 512;
            int r = k >> 2, q = k & 3;   // r 0..255
            uint32_t so = (uint32_t)(r * PADH + q * 8) * 2;
            cpa16(bbase + so, Bg + (long long)r * HID + q * 8);
        }
    }
}

// ACT: GELU on output ; OUT16: write __half instead of float
template<int ACT, int OUT16>
__global__ __launch_bounds__(256)
void gemm_h(const __half* __restrict__ A, const __half* __restrict__ Bw,
            const float* __restrict__ bias, void* __restrict__ Cv, int ldC) {
    extern __shared__ __half smem[];
    const int tid = threadIdx.x;
    const int wid = tid >> 5, lane = tid & 31;
    const int wm = wid & 3, wn = wid >> 2;
    const int grp = lane >> 2, qid = lane & 3;
    const int row0 = blockIdx.y * 128;
    const int col0 = blockIdx.x * 256;
    uint32_t sbase = smem_u32(smem);

    float acc[2][16][4];
#pragma unroll
    for (int mf = 0; mf < 2; mf++)
#pragma unroll
        for (int nf = 0; nf < 16; nf++)
#pragma unroll
            for (int i = 0; i < 4; i++) acc[mf][nf][i] = 0.f;

    const int NKC = HID / BKC;   // 32

    gemm_load_stage(sbase, 0, 0, tid, A, Bw, row0, col0);
    CPA_COMMIT();
    gemm_load_stage(sbase, 1, 1, tid, A, Bw, row0, col0);
    CPA_COMMIT();

    const int a_row = wm * 32 + (lane & 15);
    const int a_k   = (lane >> 4) * 8;
    const int b_row = wn * 128 + (lane & 7);
    const int b_k   = (lane >> 3) * 8;

    for (int kc = 0; kc < NKC; kc++) {
        int s = kc % NSTAGE;
        if (kc + 2 < NKC)
            gemm_load_stage(sbase, (kc + 2) % NSTAGE, kc + 2, tid, A, Bw, row0, col0);
        CPA_COMMIT();
        cpa_wait<2>();
        __syncthreads();

        uint32_t sAu = sbase + s * STAGEB;
        uint32_t sBu = sAu + A_BYTES;

        uint32_t afr[2][2][4];
#pragma unroll
        for (int mf = 0; mf < 2; mf++)
#pragma unroll
            for (int kk = 0; kk < 2; kk++)
                ldsm_x4(afr[mf][kk],
                        sAu + (uint32_t)((a_row + mf * 16) * PADH + kk * 16 + a_k) * 2);

#pragma unroll
        for (int nf = 0; nf < 16; nf++) {
            uint32_t bfr[4];
            ldsm_x4(bfr, sBu + (uint32_t)((b_row + nf * 8) * PADH + b_k) * 2);
            mma_f16(acc[0][nf], afr[0][0], bfr[0], bfr[1]);
            mma_f16(acc[1][nf], afr[1][0], bfr[0], bfr[1]);
            mma_f16(acc[0][nf], afr[0][1], bfr[2], bfr[3]);
            mma_f16(acc[1][nf], afr[1][1], bfr[2], bfr[3]);
        }
        __syncthreads();
    }

#pragma unroll
    for (int mf = 0; mf < 2; mf++) {
        int r0 = row0 + wm * 32 + mf * 16 + grp;
#pragma unroll
        for (int nf = 0; nf < 16; nf++) {
            int cg = col0 + wn * 128 + nf * 8 + 2 * qid;
            float bv0 = bias[cg], bv1 = bias[cg + 1];
            float v00 = acc[mf][nf][0] + bv0;
            float v01 = acc[mf][nf][1] + bv1;
            float v10 = acc[mf][nf][2] + bv0;
            float v11 = acc[mf][nf][3] + bv1;
            if (ACT) {
                v00 = 0.5f * v00 * (1.0f + erff(v00 * 0.70710678118654752f));
                v01 = 0.5f * v01 * (1.0f + erff(v01 * 0.70710678118654752f));
                v10 = 0.5f * v10 * (1.0f + erff(v10 * 0.70710678118654752f));
                v11 = 0.5f * v11 * (1.0f + erff(v11 * 0.70710678118654752f));
            }
            if (OUT16) {
                __half* C = (__half*)Cv;
                *(__half2*)&C[(long long)r0 * ldC + cg]       = __floats2half2_rn(v00, v01);
                *(__half2*)&C[(long long)(r0 + 8) * ldC + cg] = __floats2half2_rn(v10, v11);
            } else {
                float* C = (float*)Cv;
                *(float2*)&C[(long long)r0 * ldC + cg]       = make_float2(v00, v01);
                *(float2*)&C[(long long)(r0 + 8) * ldC + cg] = make_float2(v10, v11);
            }
        }
    }
}

// ============================ tensor-core flash attention (flash-v2) ============================
// Block: 256 thr / 8 warps; grid (NB*NHEAD, 2). Block = (b,h,half): q rows half*128..+127.
#define PADH2   72
#define QH_OFF  0
#define KH_OFF  (128 * PADH2 * 2)           // 18432
#define VH_OFF  (KH_OFF + 240 * PADH2 * 2)  // 52992
#define FA2_SMEM (VH_OFF + 240 * PADH2 * 2) // 87552

__global__ __launch_bounds__(256, 2)
void flash_attn2(const __half* __restrict__ qkv, const int* __restrict__ lengths,
                 __half* __restrict__ att) {
    extern __shared__ char fsm[];
    const int bh = blockIdx.x;
    const int half = blockIdx.y;
    const int b = bh >> 4, h = bh & 15;
    const int tid = threadIdx.x;
    const int w = tid >> 5, lane = tid & 31;
    const int grp = lane >> 2, qid = lane & 3;
    const int rbase = half * 128;
    const int len = lengths[b];
    const int kneed = half ? 240 : 128;

    const __half* base = qkv + (long long)b * SEQ * QKVW + h * DHEAD;

    {
        const int nQ = 128 * 8, nK = kneed * 8;
        for (int i = tid; i < nQ + 2 * nK; i += 256) {
            uint4 val = make_uint4(0, 0, 0, 0);
            char* dst;
            if (i < nQ) {
                int r = i >> 3, c = i & 7;
                int s = rbase + r;
                if (s < SEQ) val = *(const uint4*)(base + (long long)s * QKVW + c * 8);
                dst = fsm + QH_OFF + (r * PADH2 + c * 8) * 2;
            } else if (i < nQ + nK) {
                int j = i - nQ; int r = j >> 3, c = j & 7;
                val = *(const uint4*)(base + (long long)r * QKVW + 1024 + c * 8);
                dst = fsm + KH_OFF + (r * PADH2 + c * 8) * 2;
            } else {
                int j = i - nQ - nK; int r = j >> 3, c = j & 7;
                val = *(const uint4*)(base + (long long)r * QKVW + 2048 + c * 8);
                dst = fsm + VH_OFF + (r * PADH2 + c * 8) * 2;
            }
            *(uint4*)dst = val;
        }
    }
    __syncthreads();

    if (rbase + w * 16 >= SEQ) return;

    const uint32_t sb = smem_u32(fsm);
    const uint32_t QhU = sb + QH_OFF, KhU = sb + KH_OFF, VhU = sb + VH_OFF;

    const int row0g = rbase + w * 16 + grp;
    const int row1g = row0g + 8;
    const int nch = min(8 * half + w + 1, 15);

    uint32_t qf[4][4];
#pragma unroll
    for (int dk = 0; dk < 4; dk++)
        ldsm_x4(qf[dk], QhU + (uint32_t)((w * 16 + (lane & 15)) * PADH2
                                         + dk * 16 + ((lane >> 4) << 3)) * 2);

    float m0 = -1e30f, m1 = -1e30f, l0 = 0.f, l1 = 0.f;
    float acc[8][4];
#pragma unroll
    for (int nf = 0; nf < 8; nf++)
#pragma unroll
        for (int i = 0; i < 4; i++) acc[nf][i] = 0.f;

    const float sc = 1.0f / 32.0f;

    for (int kc = 0; kc < nch; kc++) {
        float S[2][4];
#pragma unroll
        for (int ng = 0; ng < 2; ng++)
#pragma unroll
            for (int i = 0; i < 4; i++) S[ng][i] = 0.f;

#pragma unroll
        for (int dg2 = 0; dg2 < 2; dg2++) {
#pragma unroll
            for (int ng = 0; ng < 2; ng++) {
                uint32_t kb[4];
                ldsm_x4(kb, KhU + (uint32_t)((kc * 16 + ng * 8 + (lane & 7)) * PADH2
                                             + dg2 * 32 + ((lane >> 3) << 3)) * 2);
                mma_f16(S[ng], qf[dg2 * 2 + 0], kb[0], kb[1]);
                mma_f16(S[ng], qf[dg2 * 2 + 1], kb[2], kb[3]);
            }
        }

        float s_[2][4];
#pragma unroll
        for (int ng = 0; ng < 2; ng++) {
            int colb = kc * 16 + ng * 8 + 2 * qid;
            s_[ng][0] = (colb     <= row0g) ? S[ng][0] * sc : -1e30f;
            s_[ng][1] = (colb + 1 <= row0g) ? S[ng][1] * sc : -1e30f;
            s_[ng][2] = (colb     <= row1g) ? S[ng][2] * sc : -1e30f;
            s_[ng][3] = (colb + 1 <= row1g) ? S[ng][3] * sc : -1e30f;
        }

        float mc0 = fmaxf(fmaxf(s_[0][0], s_[0][1]), fmaxf(s_[1][0], s_[1][1]));
        float mc1 = fmaxf(fmaxf(s_[0][2], s_[0][3]), fmaxf(s_[1][2], s_[1][3]));
        mc0 = fmaxf(mc0, __shfl_xor_sync(0xffffffff, mc0, 1));
        mc0 = fmaxf(mc0, __shfl_xor_sync(0xffffffff, mc0, 2));
        mc1 = fmaxf(mc1, __shfl_xor_sync(0xffffffff, mc1, 1));
        mc1 = fmaxf(mc1, __shfl_xor_sync(0xffffffff, mc1, 2));
        float m0n = fmaxf(m0, mc0), m1n = fmaxf(m1, mc1);
        float sf0 = __expf(m0 - m0n), sf1 = __expf(m1 - m1n);

        float p[2][4];
#pragma unroll
        for (int ng = 0; ng < 2; ng++) {
            p[ng][0] = __expf(s_[ng][0] - m0n);
            p[ng][1] = __expf(s_[ng][1] - m0n);
            p[ng][2] = __expf(s_[ng][2] - m1n);
            p[ng][3] = __expf(s_[ng][3] - m1n);
        }
        float rs0 = p[0][0] + p[0][1] + p[1][0] + p[1][1];
        float rs1 = p[0][2] + p[0][3] + p[1][2] + p[1][3];
        rs0 += __shfl_xor_sync(0xffffffff, rs0, 1);
        rs0 += __shfl_xor_sync(0xffffffff, rs0, 2);
        rs1 += __shfl_xor_sync(0xffffffff, rs1, 1);
        rs1 += __shfl_xor_sync(0xffffffff, rs1, 2);
        l0 = l0 * sf0 + rs0;  m0 = m0n;
        l1 = l1 * sf1 + rs1;  m1 = m1n;

#pragma unroll
        for (int nf = 0; nf < 8; nf++) {
            acc[nf][0] *= sf0; acc[nf][1] *= sf0;
            acc[nf][2] *= sf1; acc[nf][3] *= sf1;
        }

        uint32_t ap[4];
        {
            __half2 h0 = __floats2half2_rn(p[0][0], p[0][1]);
            __half2 h1 = __floats2half2_rn(p[0][2], p[0][3]);
            __half2 h2 = __floats2half2_rn(p[1][0], p[1][1]);
            __half2 h3 = __floats2half2_rn(p[1][2], p[1][3]);
            ap[0] = *(uint32_t*)&h0;
            ap[1] = *(uint32_t*)&h1;
            ap[2] = *(uint32_t*)&h2;
            ap[3] = *(uint32_t*)&h3;
        }

#pragma unroll
        for (int dg = 0; dg < 4; dg++) {
            uint32_t vb[4];
            ldsm_x4_t(vb, VhU + (uint32_t)((kc * 16 + (lane & 15)) * PADH2
                                           + dg * 16 + ((lane >> 4) << 3)) * 2);
            mma_f16(acc[2 * dg],     ap, vb[0], vb[1]);
            mma_f16(acc[2 * dg + 1], ap, vb[2], vb[3]);
        }
    }

    float inv0 = (row0g < len) ? (1.0f / l0) : 0.0f;
    float inv1 = (row1g < len) ? (1.0f / l1) : 0.0f;
    __half* ob0 = att + (long long)(b * SEQ + row0g) * HID + h * DHEAD;
    __half* ob1 = att + (long long)(b * SEQ + row1g) * HID + h * DHEAD;
#pragma unroll
    for (int nf = 0; nf < 8; nf++) {
        int col = (nf >> 1) * 16 + (nf & 1) * 8 + 2 * qid;
        *(__half2*)&ob0[col] = __floats2half2_rn(acc[nf][0] * inv0, acc[nf][1] * inv0);
        *(__half2*)&ob1[col] = __floats2half2_rn(acc[nf][2] * inv1, acc[nf][3] * inv1);
    }
}

// ---------------- embedding: argmax + gather + posenc (fp32 + fp16 copy) ----------------
__global__ void embed_kernel(const float* __restrict__ x,
                             const float* __restrict__ w_emb,
                             const float* __restrict__ p_emb,
                             const int*   __restrict__ lengths) {
    int bs = blockIdx.x;
    int b = bs / SEQ, s = bs % SEQ;
    __shared__ int s_tok;
    int tid = threadIdx.x;
    if (tid < 32) {
        const float* xp = x + (long long)bs * NVOCAB;
        float bv = -1e30f; int bi = 0;
        for (int c = tid; c < NVOCAB; c += 32) {
            float v = xp[c];
            if (v > bv) { bv = v; bi = c; }
        }
        for (int off = 16; off > 0; off >>= 1) {
            float ov = __shfl_down_sync(0xffffffff, bv, off);
            int   oi = __shfl_down_sync(0xffffffff, bi, off);
            if (ov > bv || (ov == bv && oi < bi)) { bv = ov; bi = oi; }
        }
        if (tid == 0) s_tok = bi;
    }
    __syncthreads();
    int tok = s_tok;
    float valid = (s < lengths[b]) ? 1.0f : 0.0f;
    const float* we = w_emb + (long long)tok * HID;
    const float* pe = p_emb + (long long)s * HID;
    float*  zp  = g_z   + (long long)bs * HID;
    __half* zph = g_z16 + (long long)bs * HID;
    for (int h = tid; h < HID; h += blockDim.x) {
        float v = we[h] * valid + pe[h];
        zp[h]  = v;
        zph[h] = __float2half(v);
    }
}

// ---------------- residual add + LayerNorm (fp16 'a' + fp32 residual) ----------------
__global__ void add_ln_kernel(const __half* __restrict__ a, const float* __restrict__ r,
                              const float* __restrict__ sc, const float* __restrict__ bi,
                              float* __restrict__ out, __half* __restrict__ out16) {
    int row = blockIdx.x;
    int tid = threadIdx.x;
    const __half* ap = a + (long long)row * HID;
    const float* rp = r + (long long)row * HID;
    float v[4];
    float s = 0.f, sq = 0.f;
#pragma unroll
    for (int j = 0; j < 4; j++) {
        int h = tid + j*256;
        v[j] = __half2float(ap[h]) + rp[h];
        s  += v[j];
        sq += v[j]*v[j];
    }
    __shared__ float red1[8], red2[8];
    for (int off = 16; off > 0; off >>= 1) {
        s  += __shfl_xor_sync(0xffffffff, s,  off);
        sq += __shfl_xor_sync(0xffffffff, sq, off);
    }
    int warp = tid >> 5, lane = tid & 31;
    if (lane == 0) { red1[warp] = s; red2[warp] = sq; }
    __syncthreads();
    if (warp == 0) {
        s  = (lane < 8) ? red1[lane] : 0.f;
        sq = (lane < 8) ? red2[lane] : 0.f;
        for (int off = 4; off > 0; off >>= 1) {
            s  += __shfl_xor_sync(0xffffffff, s,  off);
            sq += __shfl_xor_sync(0xffffffff, sq, off);
        }
        if (lane == 0) { red1[0] = s; red2[0] = sq; }
    }
    __syncthreads();
    float mean = red1[0] * (1.0f / HID);
    float var  = red2[0] * (1.0f / HID) - mean * mean;
    float rstd = rsqrtf(var + 1e-5f);
    float*  op  = out   + (long long)row * HID;
    __half* oph = out16 + (long long)row * HID;
#pragma unroll
    for (int j = 0; j < 4; j++) {
        int h = tid + j*256;
        float o = (v[j] - mean) * rstd * sc[h] + bi[h];
        op[h]  = o;
        oph[h] = __float2half(o);
    }
}

// ---------------- mean-pool ----------------
__global__ void pool_kernel() {
    int b = blockIdx.y;
    int h = blockIdx.x * 256 + threadIdx.x;
    float s = 0.f;
    const float* zp = g_z + (long long)b * SEQ * HID + h;
    for (int si = 0; si < SEQ; si++)
        s += zp[(long long)si * HID];
    g_pool[b * HID + h] = s * (1.0f / SEQ);
}

// ---------------- classifier head + softmax(4) ----------------
__global__ void head_kernel(const float* __restrict__ Wfc, const float* __restrict__ bfc,
                            float* __restrict__ out) {
    int b = blockIdx.x;
    int tid = threadIdx.x;
    float p[4] = {0.f, 0.f, 0.f, 0.f};
    const float* zp = g_pool + b * HID;
    for (int h = tid; h < HID; h += 256) {
        float zv = zp[h];
#pragma unroll
        for (int c = 0; c < 4; c++) p[c] += zv * Wfc[h*4 + c];
    }
    __shared__ float red[4][256];
#pragma unroll
    for (int c = 0; c < 4; c++) red[c][tid] = p[c];
    __syncthreads();
    for (int str = 128; str > 0; str >>= 1) {
        if (tid < str)
#pragma unroll
            for (int c = 0; c < 4; c++) red[c][tid] += red[c][tid + str];
        __syncthreads();
    }
    if (tid == 0) {
        float l[4];
        float m = -1e30f;
#pragma unroll
        for (int c = 0; c < 4; c++) { l[c] = red[c][0] + bfc[c]; m = fmaxf(m, l[c]); }
        float ssum = 0.f;
#pragma unroll
        for (int c = 0; c < 4; c++) { l[c] = __expf(l[c] - m); ssum += l[c]; }
        float inv = 1.0f / ssum;
#pragma unroll
        for (int c = 0; c < 4; c++) out[b*4 + c] = l[c] * inv;
    }
}

// ---------------- host orchestration ----------------
extern "C" void kernel_launch(void* const* d_in, const int* in_sizes, int n_in,
                              void* d_out, int out_size) {
    const float* x     = (const float*)d_in[0];
    const float* w_emb = (const float*)d_in[1];
    const float* p_emb = (const float*)d_in[2];
    const float* Wq    = (const float*)d_in[3];
    const float* bq    = (const float*)d_in[4];
    const float* Wk    = (const float*)d_in[5];
    const float* bk    = (const float*)d_in[6];
    const float* Wv    = (const float*)d_in[7];
    const float* bv    = (const float*)d_in[8];
    const float* W1    = (const float*)d_in[9];
    const float* b1    = (const float*)d_in[10];
    const float* W2    = (const float*)d_in[11];
    const float* b2    = (const float*)d_in[12];
    const float* ln1_s = (const float*)d_in[13];
    const float* ln1_b = (const float*)d_in[14];
    const float* ln2_s = (const float*)d_in[15];
    const float* ln2_b = (const float*)d_in[16];
    const float* Wfc   = (const float*)d_in[17];
    const float* bfc   = (const float*)d_in[18];
    const int*   lengths = (const int*)d_in[19];
    float* out = (float*)d_out;

    float *pz, *pz1, *pbqkv;
    __half *pz16, *pz116, *pffh16, *pwqkv16, *pw1216, *pqkv16, *patt16;
    cudaGetSymbolAddress((void**)&pz,     g_z);
    cudaGetSymbolAddress((void**)&pz16,   g_z16);
    cudaGetSymbolAddress((void**)&pqkv16, g_qkv16);
    cudaGetSymbolAddress((void**)&patt16, g_att16);
    cudaGetSymbolAddress((void**)&pz1,    g_z1);
    cudaGetSymbolAddress((void**)&pz116,  g_z116);
    cudaGetSymbolAddress((void**)&pffh16, g_ffh16);
    cudaGetSymbolAddress((void**)&pwqkv16,g_wqkv16);
    cudaGetSymbolAddress((void**)&pw1216, g_w1216);
    cudaGetSymbolAddress((void**)&pbqkv,  g_bqkv);

    cudaFuncSetAttribute((const void*)gemm_h<0,1>, cudaFuncAttributeMaxDynamicSharedMemorySize, GEMM_SMEM);
    cudaFuncSetAttribute((const void*)gemm_h<1,1>, cudaFuncAttributeMaxDynamicSharedMemorySize, GEMM_SMEM);
    cudaFuncSetAttribute((const void*)flash_attn2, cudaFuncAttributeMaxDynamicSharedMemorySize, FA2_SMEM);

    const long long MAT = (long long)HID * HID;

    dim3 tgrid(HID/32, HID/32, NLAYER);
    dim3 tblk(32, 8);
    transpose_h_kernel<<<tgrid, tblk>>>(Wq, pwqkv16 + 0*MAT, 3*MAT);
    transpose_h_kernel<<<tgrid, tblk>>>(Wk, pwqkv16 + 1*MAT, 3*MAT);
    transpose_h_kernel<<<tgrid, tblk>>>(Wv, pwqkv16 + 2*MAT, 3*MAT);
    transpose_h_kernel<<<tgrid, tblk>>>(W1, pw1216  + 0*MAT, 2*MAT);
    transpose_h_kernel<<<tgrid, tblk>>>(W2, pw1216  + 1*MAT, 2*MAT);
    biaspack_kernel<<<(NLAYER*QKVW + 255)/256, 256>>>(bq, bk, bv);

    embed_kernel<<<BS_TOT, 256>>>(x, w_emb, p_emb, lengths);

    dim3 qkv_grid(QKVW/256, BS_TOT/128);   // (12, 60)
    dim3 ff_grid(HID/256, BS_TOT/128);     // (4, 60)
    dim3 fa_grid(NB*NHEAD, 2);             // (512, 2)

    for (int i = 0; i < NLAYER; i++) {
        long long bOff = (long long)i * HID;
        gemm_h<0,1><<<qkv_grid, 256, GEMM_SMEM>>>(pz16, pwqkv16 + (long long)i*3*MAT,
                                                  pbqkv + (long long)i*QKVW, pqkv16, QKVW);
        flash_attn2<<<fa_grid, 256, FA2_SMEM>>>(pqkv16, lengths, patt16);
        add_ln_kernel<<<BS_TOT, 256>>>(patt16, pz, ln1_s + bOff, ln1_b + bOff, pz1, pz116);
        gemm_h<1,1><<<ff_grid, 256, GEMM_SMEM>>>(pz116, pw1216 + (long long)i*2*MAT,
                                                 b1 + bOff, pffh16, HID);
        gemm_h<0,1><<<ff_grid, 256, GEMM_SMEM>>>(pffh16, pw1216 + (long long)i*2*MAT + MAT,
                                                 b2 + bOff, patt16, HID);
        add_ln_kernel<<<BS_TOT, 256>>>(patt16, pz1, ln2_s + bOff, ln2_b + bOff, pz, pz16);
    }

    pool_kernel<<<dim3(HID/256, NB), 256>>>();
    head_kernel<<<NB, 256>>>(Wfc, bfc, out);
}

// round 14
// speedup vs baseline: 1.0993x; 1.0993x over previous
#include <cuda_runtime.h>
#include <cuda_fp16.h>
#include <math.h>
#include <cstdint>

#define NB     32
#define SEQ    240
#define HID    1024
#define NLAYER 8
#define NHEAD  16
#define DHEAD  64
#define NVOCAB 48
#define BS_TOT (NB*SEQ)   // 7680
#define QKVW   3072

// ---------------- device scratch (no allocation allowed) ----------------
__device__ float  g_z   [BS_TOT*HID];
__device__ __half g_z16 [BS_TOT*HID];
__device__ __half g_qkv16[(long long)BS_TOT*QKVW];
__device__ __half g_att16[BS_TOT*HID];     // attention out & FFN out (fp16)
__device__ float  g_z1  [BS_TOT*HID];
__device__ __half g_z116[BS_TOT*HID];
__device__ __half g_ffh16[BS_TOT*HID];
__device__ float  g_pool[NB*HID];
__device__ __half g_wqkv16[(long long)NLAYER*3*HID*HID];  // [L][3072][1024] transposed fp16
__device__ __half g_w1216 [(long long)NLAYER*2*HID*HID];  // [L][W1t|W2t] fp16
__device__ float  g_bqkv[NLAYER*QKVW];

// ============================ helpers ============================
__device__ __forceinline__ uint32_t smem_u32(const void* p) {
    return (uint32_t)__cvta_generic_to_shared(p);
}
__device__ __forceinline__ void cpa16(uint32_t dst, const void* src) {
    asm volatile("cp.async.cg.shared.global [%0], [%1], 16;" :: "r"(dst), "l"(src));
}
#define CPA_COMMIT() asm volatile("cp.async.commit_group;" ::: "memory")
template<int N> __device__ __forceinline__ void cpa_wait() {
    asm volatile("cp.async.wait_group %0;" :: "n"(N) : "memory");
}

__device__ __forceinline__ void mma_f16(float* c, const uint32_t* a, uint32_t b0, uint32_t b1) {
    asm volatile(
        "mma.sync.aligned.m16n8k16.row.col.f32.f16.f16.f32 "
        "{%0,%1,%2,%3}, {%4,%5,%6,%7}, {%8,%9}, {%0,%1,%2,%3};"
        : "+f"(c[0]), "+f"(c[1]), "+f"(c[2]), "+f"(c[3])
        : "r"(a[0]), "r"(a[1]), "r"(a[2]), "r"(a[3]), "r"(b0), "r"(b1));
}
__device__ __forceinline__ void ldsm_x4(uint32_t* r, uint32_t addr) {
    asm volatile("ldmatrix.sync.aligned.m8n8.x4.shared.b16 {%0,%1,%2,%3}, [%4];"
        : "=r"(r[0]), "=r"(r[1]), "=r"(r[2]), "=r"(r[3]) : "r"(addr));
}
__device__ __forceinline__ void ldsm_x4_t(uint32_t* r, uint32_t addr) {
    asm volatile("ldmatrix.sync.aligned.m8n8.x4.trans.shared.b16 {%0,%1,%2,%3}, [%4];"
        : "=r"(r[0]), "=r"(r[1]), "=r"(r[2]), "=r"(r[3]) : "r"(addr));
}

// ============================ weight transpose -> fp16 ============================
__global__ void transpose_h_kernel(const float* __restrict__ src, __half* __restrict__ dst,
                                   long long dstZ) {
    __shared__ float t[32][33];
    long long smoff = (long long)blockIdx.z * HID * HID;
    long long dmoff = (long long)blockIdx.z * dstZ;
    int x0 = blockIdx.x * 32, y0 = blockIdx.y * 32;
    int tx = threadIdx.x, ty = threadIdx.y;  // 32 x 8
#pragma unroll
    for (int j = 0; j < 32; j += 8)
        t[ty + j][tx] = src[smoff + (long long)(y0 + ty + j) * HID + x0 + tx];
    __syncthreads();
#pragma unroll
    for (int j = 0; j < 32; j += 8)
        dst[dmoff + (long long)(x0 + ty + j) * HID + y0 + tx] = __float2half(t[tx][ty + j]);
}

// bias pack: g_bqkv[l][t*1024+n]
__global__ void biaspack_kernel(const float* __restrict__ bq, const float* __restrict__ bk,
                                const float* __restrict__ bv) {
    int idx = blockIdx.x * 256 + threadIdx.x;
    if (idx >= NLAYER * QKVW) return;
    int l = idx / QKVW, r = idx % QKVW;
    int t = r >> 10, n = r & 1023;
    const float* src = (t == 0) ? bq : (t == 1) ? bk : bv;
    g_bqkv[idx] = src[l * HID + n];
}

// ============================ fp16 mma.sync GEMM (R12 proven shape) ============================
// C[M,N] = A[M,K] @ Wt^T + bias ; A fp16 [M,K] (lda=HID), Wt fp16 [N,K].
// BM=128, BN=128, BK=32 halves; 256 threads; warp grid 4x2, warp tile 32x64; 2 CTA/SM.
#define BKC   32
#define PADH  40
#define ABYTES (128 * PADH * 2)          // 10240
#define STAGEB (2 * ABYTES)              // 20480
#define NSTAGE 3
#define GEMM_SMEM (NSTAGE * STAGEB)      // 61440

__device__ __forceinline__ void gemm_load_stage(uint32_t sbase, int s, int kc, int tid,
                                                const __half* __restrict__ A,
                                                const __half* __restrict__ Bw,
                                                int row0, int col0) {
    uint32_t abase = sbase + s * STAGEB;
    uint32_t bbase = abase + ABYTES;
    const __half* Ag = A  + (long long)row0 * HID + kc * BKC;
    const __half* Bg = Bw + (long long)col0 * HID + kc * BKC;
#pragma unroll
    for (int j = 0; j < 2; j++) {
        int c = tid + j * 256;
        int r = c >> 2, q = c & 3;
        uint32_t so = (uint32_t)(r * PADH + q * 8) * 2;
        cpa16(abase + so, Ag + (long long)r * HID + q * 8);
        cpa16(bbase + so, Bg + (long long)r * HID + q * 8);
    }
}

// ACT: GELU on output ; OUT16: write __half instead of float
template<int ACT, int OUT16>
__global__ __launch_bounds__(256, 2)
void gemm_h(const __half* __restrict__ A, const __half* __restrict__ Bw,
            const float* __restrict__ bias, void* __restrict__ Cv, int ldC) {
    extern __shared__ __half smem[];
    const int tid = threadIdx.x;
    const int wid = tid >> 5, lane = tid & 31;
    const int wm = wid & 3, wn = wid >> 2;
    const int grp = lane >> 2, qid = lane & 3;
    const int row0 = blockIdx.y * 128;
    const int col0 = blockIdx.x * 128;
    uint32_t sbase = smem_u32(smem);

    float acc[2][8][4];
#pragma unroll
    for (int mf = 0; mf < 2; mf++)
#pragma unroll
        for (int nf = 0; nf < 8; nf++)
#pragma unroll
            for (int i = 0; i < 4; i++) acc[mf][nf][i] = 0.f;

    const int NKC = HID / BKC;   // 32

    gemm_load_stage(sbase, 0, 0, tid, A, Bw, row0, col0);
    CPA_COMMIT();
    gemm_load_stage(sbase, 1, 1, tid, A, Bw, row0, col0);
    CPA_COMMIT();

    const int a_row = wm * 32 + (lane & 15);
    const int a_k   = (lane >> 4) * 8;
    const int b_row = wn * 64 + (lane & 7);
    const int b_k   = (lane >> 3) * 8;

    for (int kc = 0; kc < NKC; kc++) {
        int s = kc % NSTAGE;
        if (kc + 2 < NKC)
            gemm_load_stage(sbase, (kc + 2) % NSTAGE, kc + 2, tid, A, Bw, row0, col0);
        CPA_COMMIT();
        cpa_wait<2>();
        __syncthreads();

        uint32_t sAu = sbase + s * STAGEB;
        uint32_t sBu = sAu + ABYTES;

        uint32_t afr[2][2][4];
#pragma unroll
        for (int mf = 0; mf < 2; mf++)
#pragma unroll
            for (int kk = 0; kk < 2; kk++)
                ldsm_x4(afr[mf][kk],
                        sAu + (uint32_t)((a_row + mf * 16) * PADH + kk * 16 + a_k) * 2);

#pragma unroll
        for (int nf = 0; nf < 8; nf++) {
            uint32_t bfr[4];
            ldsm_x4(bfr, sBu + (uint32_t)((b_row + nf * 8) * PADH + b_k) * 2);
            mma_f16(acc[0][nf], afr[0][0], bfr[0], bfr[1]);
            mma_f16(acc[1][nf], afr[1][0], bfr[0], bfr[1]);
            mma_f16(acc[0][nf], afr[0][1], bfr[2], bfr[3]);
            mma_f16(acc[1][nf], afr[1][1], bfr[2], bfr[3]);
        }
        __syncthreads();
    }

#pragma unroll
    for (int mf = 0; mf < 2; mf++) {
        int r0 = row0 + wm * 32 + mf * 16 + grp;
#pragma unroll
        for (int nf = 0; nf < 8; nf++) {
            int cg = col0 + wn * 64 + nf * 8 + 2 * qid;
            float bv0 = bias[cg], bv1 = bias[cg + 1];
            float v00 = acc[mf][nf][0] + bv0;
            float v01 = acc[mf][nf][1] + bv1;
            float v10 = acc[mf][nf][2] + bv0;
            float v11 = acc[mf][nf][3] + bv1;
            if (ACT) {
                v00 = 0.5f * v00 * (1.0f + erff(v00 * 0.70710678118654752f));
                v01 = 0.5f * v01 * (1.0f + erff(v01 * 0.70710678118654752f));
                v10 = 0.5f * v10 * (1.0f + erff(v10 * 0.70710678118654752f));
                v11 = 0.5f * v11 * (1.0f + erff(v11 * 0.70710678118654752f));
            }
            if (OUT16) {
                __half* C = (__half*)Cv;
                *(__half2*)&C[(long long)r0 * ldC + cg]       = __floats2half2_rn(v00, v01);
                *(__half2*)&C[(long long)(r0 + 8) * ldC + cg] = __floats2half2_rn(v10, v11);
            } else {
                float* C = (float*)Cv;
                *(float2*)&C[(long long)r0 * ldC + cg]       = make_float2(v00, v01);
                *(float2*)&C[(long long)(r0 + 8) * ldC + cg] = make_float2(v10, v11);
            }
        }
    }
}

// ============================ tensor-core flash attention (flash-v2) ============================
// Block: 256 thr / 8 warps; grid (NB*NHEAD, 2). Block = (b,h,half): q rows half*128..+127.
#define PADH2   72
#define QH_OFF  0
#define KH_OFF  (128 * PADH2 * 2)           // 18432
#define VH_OFF  (KH_OFF + 240 * PADH2 * 2)  // 52992
#define FA2_SMEM (VH_OFF + 240 * PADH2 * 2) // 87552

__global__ __launch_bounds__(256, 2)
void flash_attn2(const __half* __restrict__ qkv, const int* __restrict__ lengths,
                 __half* __restrict__ att) {
    extern __shared__ char fsm[];
    const int bh = blockIdx.x;
    const int half = blockIdx.y;
    const int b = bh >> 4, h = bh & 15;
    const int tid = threadIdx.x;
    const int w = tid >> 5, lane = tid & 31;
    const int grp = lane >> 2, qid = lane & 3;
    const int rbase = half * 128;
    const int len = lengths[b];
    const int kneed = half ? 240 : 128;

    const __half* base = qkv + (long long)b * SEQ * QKVW + h * DHEAD;

    {
        const int nQ = 128 * 8, nK = kneed * 8;
        for (int i = tid; i < nQ + 2 * nK; i += 256) {
            uint4 val = make_uint4(0, 0, 0, 0);
            char* dst;
            if (i < nQ) {
                int r = i >> 3, c = i & 7;
                int s = rbase + r;
                if (s < SEQ) val = *(const uint4*)(base + (long long)s * QKVW + c * 8);
                dst = fsm + QH_OFF + (r * PADH2 + c * 8) * 2;
            } else if (i < nQ + nK) {
                int j = i - nQ; int r = j >> 3, c = j & 7;
                val = *(const uint4*)(base + (long long)r * QKVW + 1024 + c * 8);
                dst = fsm + KH_OFF + (r * PADH2 + c * 8) * 2;
            } else {
                int j = i - nQ - nK; int r = j >> 3, c = j & 7;
                val = *(const uint4*)(base + (long long)r * QKVW + 2048 + c * 8);
                dst = fsm + VH_OFF + (r * PADH2 + c * 8) * 2;
            }
            *(uint4*)dst = val;
        }
    }
    __syncthreads();

    if (rbase + w * 16 >= SEQ) return;

    const uint32_t sb = smem_u32(fsm);
    const uint32_t QhU = sb + QH_OFF, KhU = sb + KH_OFF, VhU = sb + VH_OFF;

    const int row0g = rbase + w * 16 + grp;
    const int row1g = row0g + 8;
    const int nch = min(8 * half + w + 1, 15);

    uint32_t qf[4][4];
#pragma unroll
    for (int dk = 0; dk < 4; dk++)
        ldsm_x4(qf[dk], QhU + (uint32_t)((w * 16 + (lane & 15)) * PADH2
                                         + dk * 16 + ((lane >> 4) << 3)) * 2);

    float m0 = -1e30f, m1 = -1e30f, l0 = 0.f, l1 = 0.f;
    float acc[8][4];
#pragma unroll
    for (int nf = 0; nf < 8; nf++)
#pragma unroll
        for (int i = 0; i < 4; i++) acc[nf][i] = 0.f;

    const float sc = 1.0f / 32.0f;

    for (int kc = 0; kc < nch; kc++) {
        float S[2][4];
#pragma unroll
        for (int ng = 0; ng < 2; ng++)
#pragma unroll
            for (int i = 0; i < 4; i++) S[ng][i] = 0.f;

#pragma unroll
        for (int dg2 = 0; dg2 < 2; dg2++) {
#pragma unroll
            for (int ng = 0; ng < 2; ng++) {
                uint32_t kb[4];
                ldsm_x4(kb, KhU + (uint32_t)((kc * 16 + ng * 8 + (lane & 7)) * PADH2
                                             + dg2 * 32 + ((lane >> 3) << 3)) * 2);
                mma_f16(S[ng], qf[dg2 * 2 + 0], kb[0], kb[1]);
                mma_f16(S[ng], qf[dg2 * 2 + 1], kb[2], kb[3]);
            }
        }

        float s_[2][4];
#pragma unroll
        for (int ng = 0; ng < 2; ng++) {
            int colb = kc * 16 + ng * 8 + 2 * qid;
            s_[ng][0] = (colb     <= row0g) ? S[ng][0] * sc : -1e30f;
            s_[ng][1] = (colb + 1 <= row0g) ? S[ng][1] * sc : -1e30f;
            s_[ng][2] = (colb     <= row1g) ? S[ng][2] * sc : -1e30f;
            s_[ng][3] = (colb + 1 <= row1g) ? S[ng][3] * sc : -1e30f;
        }

        float mc0 = fmaxf(fmaxf(s_[0][0], s_[0][1]), fmaxf(s_[1][0], s_[1][1]));
        float mc1 = fmaxf(fmaxf(s_[0][2], s_[0][3]), fmaxf(s_[1][2], s_[1][3]));
        mc0 = fmaxf(mc0, __shfl_xor_sync(0xffffffff, mc0, 1));
        mc0 = fmaxf(mc0, __shfl_xor_sync(0xffffffff, mc0, 2));
        mc1 = fmaxf(mc1, __shfl_xor_sync(0xffffffff, mc1, 1));
        mc1 = fmaxf(mc1, __shfl_xor_sync(0xffffffff, mc1, 2));
        float m0n = fmaxf(m0, mc0), m1n = fmaxf(m1, mc1);
        float sf0 = __expf(m0 - m0n), sf1 = __expf(m1 - m1n);

        float p[2][4];
#pragma unroll
        for (int ng = 0; ng < 2; ng++) {
            p[ng][0] = __expf(s_[ng][0] - m0n);
            p[ng][1] = __expf(s_[ng][1] - m0n);
            p[ng][2] = __expf(s_[ng][2] - m1n);
            p[ng][3] = __expf(s_[ng][3] - m1n);
        }
        float rs0 = p[0][0] + p[0][1] + p[1][0] + p[1][1];
        float rs1 = p[0][2] + p[0][3] + p[1][2] + p[1][3];
        rs0 += __shfl_xor_sync(0xffffffff, rs0, 1);
        rs0 += __shfl_xor_sync(0xffffffff, rs0, 2);
        rs1 += __shfl_xor_sync(0xffffffff, rs1, 1);
        rs1 += __shfl_xor_sync(0xffffffff, rs1, 2);
        l0 = l0 * sf0 + rs0;  m0 = m0n;
        l1 = l1 * sf1 + rs1;  m1 = m1n;

#pragma unroll
        for (int nf = 0; nf < 8; nf++) {
            acc[nf][0] *= sf0; acc[nf][1] *= sf0;
            acc[nf][2] *= sf1; acc[nf][3] *= sf1;
        }

        uint32_t ap[4];
        {
            __half2 h0 = __floats2half2_rn(p[0][0], p[0][1]);
            __half2 h1 = __floats2half2_rn(p[0][2], p[0][3]);
            __half2 h2 = __floats2half2_rn(p[1][0], p[1][1]);
            __half2 h3 = __floats2half2_rn(p[1][2], p[1][3]);
            ap[0] = *(uint32_t*)&h0;
            ap[1] = *(uint32_t*)&h1;
            ap[2] = *(uint32_t*)&h2;
            ap[3] = *(uint32_t*)&h3;
        }

#pragma unroll
        for (int dg = 0; dg < 4; dg++) {
            uint32_t vb[4];
            ldsm_x4_t(vb, VhU + (uint32_t)((kc * 16 + (lane & 15)) * PADH2
                                           + dg * 16 + ((lane >> 4) << 3)) * 2);
            mma_f16(acc[2 * dg],     ap, vb[0], vb[1]);
            mma_f16(acc[2 * dg + 1], ap, vb[2], vb[3]);
        }
    }

    float inv0 = (row0g < len) ? (1.0f / l0) : 0.0f;
    float inv1 = (row1g < len) ? (1.0f / l1) : 0.0f;
    __half* ob0 = att + (long long)(b * SEQ + row0g) * HID + h * DHEAD;
    __half* ob1 = att + (long long)(b * SEQ + row1g) * HID + h * DHEAD;
#pragma unroll
    for (int nf = 0; nf < 8; nf++) {
        int col = (nf >> 1) * 16 + (nf & 1) * 8 + 2 * qid;
        *(__half2*)&ob0[col] = __floats2half2_rn(acc[nf][0] * inv0, acc[nf][1] * inv0);
        *(__half2*)&ob1[col] = __floats2half2_rn(acc[nf][2] * inv1, acc[nf][3] * inv1);
    }
}

// ---------------- embedding: argmax + gather + posenc (fp32 + fp16 copy) ----------------
__global__ void embed_kernel(const float* __restrict__ x,
                             const float* __restrict__ w_emb,
                             const float* __restrict__ p_emb,
                             const int*   __restrict__ lengths) {
    int bs = blockIdx.x;
    int b = bs / SEQ, s = bs % SEQ;
    __shared__ int s_tok;
    int tid = threadIdx.x;
    if (tid < 32) {
        const float* xp = x + (long long)bs * NVOCAB;
        float bv = -1e30f; int bi = 0;
        for (int c = tid; c < NVOCAB; c += 32) {
            float v = xp[c];
            if (v > bv) { bv = v; bi = c; }
        }
        for (int off = 16; off > 0; off >>= 1) {
            float ov = __shfl_down_sync(0xffffffff, bv, off);
            int   oi = __shfl_down_sync(0xffffffff, bi, off);
            if (ov > bv || (ov == bv && oi < bi)) { bv = ov; bi = oi; }
        }
        if (tid == 0) s_tok = bi;
    }
    __syncthreads();
    int tok = s_tok;
    float valid = (s < lengths[b]) ? 1.0f : 0.0f;
    const float* we = w_emb + (long long)tok * HID;
    const float* pe = p_emb + (long long)s * HID;
    float*  zp  = g_z   + (long long)bs * HID;
    __half* zph = g_z16 + (long long)bs * HID;
    for (int h = tid; h < HID; h += blockDim.x) {
        float v = we[h] * valid + pe[h];
        zp[h]  = v;
        zph[h] = __float2half(v);
    }
}

// ---------------- residual add + LayerNorm (fp16 'a' + fp32 residual) ----------------
__global__ void add_ln_kernel(const __half* __restrict__ a, const float* __restrict__ r,
                              const float* __restrict__ sc, const float* __restrict__ bi,
                              float* __restrict__ out, __half* __restrict__ out16) {
    int row = blockIdx.x;
    int tid = threadIdx.x;
    const __half* ap = a + (long long)row * HID;
    const float* rp = r + (long long)row * HID;
    float v[4];
    float s = 0.f, sq = 0.f;
#pragma unroll
    for (int j = 0; j < 4; j++) {
        int h = tid + j*256;
        v[j] = __half2float(ap[h]) + rp[h];
        s  += v[j];
        sq += v[j]*v[j];
    }
    __shared__ float red1[8], red2[8];
    for (int off = 16; off > 0; off >>= 1) {
        s  += __shfl_xor_sync(0xffffffff, s,  off);
        sq += __shfl_xor_sync(0xffffffff, sq, off);
    }
    int warp = tid >> 5, lane = tid & 31;
    if (lane == 0) { red1[warp] = s; red2[warp] = sq; }
    __syncthreads();
    if (warp == 0) {
        s  = (lane < 8) ? red1[lane] : 0.f;
        sq = (lane < 8) ? red2[lane] : 0.f;
        for (int off = 4; off > 0; off >>= 1) {
            s  += __shfl_xor_sync(0xffffffff, s,  off);
            sq += __shfl_xor_sync(0xffffffff, sq, off);
        }
        if (lane == 0) { red1[0] = s; red2[0] = sq; }
    }
    __syncthreads();
    float mean = red1[0] * (1.0f / HID);
    float var  = red2[0] * (1.0f / HID) - mean * mean;
    float rstd = rsqrtf(var + 1e-5f);
    float*  op  = out   + (long long)row * HID;
    __half* oph = out16 + (long long)row * HID;
#pragma unroll
    for (int j = 0; j < 4; j++) {
        int h = tid + j*256;
        float o = (v[j] - mean) * rstd * sc[h] + bi[h];
        op[h]  = o;
        oph[h] = __float2half(o);
    }
}

// ---------------- mean-pool ----------------
__global__ void pool_kernel() {
    int b = blockIdx.y;
    int h = blockIdx.x * 256 + threadIdx.x;
    float s = 0.f;
    const float* zp = g_z + (long long)b * SEQ * HID + h;
    for (int si = 0; si < SEQ; si++)
        s += zp[(long long)si * HID];
    g_pool[b * HID + h] = s * (1.0f / SEQ);
}

// ---------------- classifier head + softmax(4) ----------------
__global__ void head_kernel(const float* __restrict__ Wfc, const float* __restrict__ bfc,
                            float* __restrict__ out) {
    int b = blockIdx.x;
    int tid = threadIdx.x;
    float p[4] = {0.f, 0.f, 0.f, 0.f};
    const float* zp = g_pool + b * HID;
    for (int h = tid; h < HID; h += 256) {
        float zv = zp[h];
#pragma unroll
        for (int c = 0; c < 4; c++) p[c] += zv * Wfc[h*4 + c];
    }
    __shared__ float red[4][256];
#pragma unroll
    for (int c = 0; c < 4; c++) red[c][tid] = p[c];
    __syncthreads();
    for (int str = 128; str > 0; str >>= 1) {
        if (tid < str)
#pragma unroll
            for (int c = 0; c < 4; c++) red[c][tid] += red[c][tid + str];
        __syncthreads();
    }
    if (tid == 0) {
        float l[4];
        float m = -1e30f;
#pragma unroll
        for (int c = 0; c < 4; c++) { l[c] = red[c][0] + bfc[c]; m = fmaxf(m, l[c]); }
        float ssum = 0.f;
#pragma unroll
        for (int c = 0; c < 4; c++) { l[c] = __expf(l[c] - m); ssum += l[c]; }
        float inv = 1.0f / ssum;
#pragma unroll
        for (int c = 0; c < 4; c++) out[b*4 + c] = l[c] * inv;
    }
}

// ---------------- host orchestration ----------------
extern "C" void kernel_launch(void* const* d_in, const int* in_sizes, int n_in,
                              void* d_out, int out_size) {
    const float* x     = (const float*)d_in[0];
    const float* w_emb = (const float*)d_in[1];
    const float* p_emb = (const float*)d_in[2];
    const float* Wq    = (const float*)d_in[3];
    const float* bq    = (const float*)d_in[4];
    const float* Wk    = (const float*)d_in[5];
    const float* bk    = (const float*)d_in[6];
    const float* Wv    = (const float*)d_in[7];
    const float* bv    = (const float*)d_in[8];
    const float* W1    = (const float*)d_in[9];
    const float* b1    = (const float*)d_in[10];
    const float* W2    = (const float*)d_in[11];
    const float* b2    = (const float*)d_in[12];
    const float* ln1_s = (const float*)d_in[13];
    const float* ln1_b = (const float*)d_in[14];
    const float* ln2_s = (const float*)d_in[15];
    const float* ln2_b = (const float*)d_in[16];
    const float* Wfc   = (const float*)d_in[17];
    const float* bfc   = (const float*)d_in[18];
    const int*   lengths = (const int*)d_in[19];
    float* out = (float*)d_out;

    float *pz, *pz1, *pbqkv;
    __half *pz16, *pz116, *pffh16, *pwqkv16, *pw1216, *pqkv16, *patt16;
    cudaGetSymbolAddress((void**)&pz,     g_z);
    cudaGetSymbolAddress((void**)&pz16,   g_z16);
    cudaGetSymbolAddress((void**)&pqkv16, g_qkv16);
    cudaGetSymbolAddress((void**)&patt16, g_att16);
    cudaGetSymbolAddress((void**)&pz1,    g_z1);
    cudaGetSymbolAddress((void**)&pz116,  g_z116);
    cudaGetSymbolAddress((void**)&pffh16, g_ffh16);
    cudaGetSymbolAddress((void**)&pwqkv16,g_wqkv16);
    cudaGetSymbolAddress((void**)&pw1216, g_w1216);
    cudaGetSymbolAddress((void**)&pbqkv,  g_bqkv);

    cudaFuncSetAttribute((const void*)gemm_h<0,1>, cudaFuncAttributeMaxDynamicSharedMemorySize, GEMM_SMEM);
    cudaFuncSetAttribute((const void*)gemm_h<1,1>, cudaFuncAttributeMaxDynamicSharedMemorySize, GEMM_SMEM);
    cudaFuncSetAttribute((const void*)flash_attn2, cudaFuncAttributeMaxDynamicSharedMemorySize, FA2_SMEM);

    const long long MAT = (long long)HID * HID;

    dim3 tgrid(HID/32, HID/32, NLAYER);
    dim3 tblk(32, 8);
    transpose_h_kernel<<<tgrid, tblk>>>(Wq, pwqkv16 + 0*MAT, 3*MAT);
    transpose_h_kernel<<<tgrid, tblk>>>(Wk, pwqkv16 + 1*MAT, 3*MAT);
    transpose_h_kernel<<<tgrid, tblk>>>(Wv, pwqkv16 + 2*MAT, 3*MAT);
    transpose_h_kernel<<<tgrid, tblk>>>(W1, pw1216  + 0*MAT, 2*MAT);
    transpose_h_kernel<<<tgrid, tblk>>>(W2, pw1216  + 1*MAT, 2*MAT);
    biaspack_kernel<<<(NLAYER*QKVW + 255)/256, 256>>>(bq, bk, bv);

    embed_kernel<<<BS_TOT, 256>>>(x, w_emb, p_emb, lengths);

    dim3 qkv_grid(QKVW/128, BS_TOT/128);   // (24, 60)
    dim3 ff_grid(HID/128, BS_TOT/128);     // (8, 60)
    dim3 fa_grid(NB*NHEAD, 2);             // (512, 2)

    for (int i = 0; i < NLAYER; i++) {
        long long bOff = (long long)i * HID;
        gemm_h<0,1><<<qkv_grid, 256, GEMM_SMEM>>>(pz16, pwqkv16 + (long long)i*3*MAT,
                                                  pbqkv + (long long)i*QKVW, pqkv16, QKVW);
        flash_attn2<<<fa_grid, 256, FA2_SMEM>>>(pqkv16, lengths, patt16);
        add_ln_kernel<<<BS_TOT, 256>>>(patt16, pz, ln1_s + bOff, ln1_b + bOff, pz1, pz116);
        gemm_h<1,1><<<ff_grid, 256, GEMM_SMEM>>>(pz116, pw1216 + (long long)i*2*MAT,
                                                 b1 + bOff, pffh16, HID);
        gemm_h<0,1><<<ff_grid, 256, GEMM_SMEM>>>(pffh16, pw1216 + (long long)i*2*MAT + MAT,
                                                 b2 + bOff, patt16, HID);
        add_ln_kernel<<<BS_TOT, 256>>>(patt16, pz1, ln2_s + bOff, ln2_b + bOff, pz, pz16);
    }

    pool_kernel<<<dim3(HID/256, NB), 256>>>();
    head_kernel<<<NB, 256>>>(Wfc, bfc, out);
}

// round 15
// speedup vs baseline: 1.1281x; 1.0263x over previous
#include <cuda_runtime.h>
#include <cuda_fp16.h>
#include <math.h>
#include <cstdint>

#define NB     32
#define SEQ    240
#define HID    1024
#define NLAYER 8
#define NHEAD  16
#define DHEAD  64
#define NVOCAB 48
#define BS_TOT (NB*SEQ)   // 7680
#define QKVW   3072

// ---------------- device scratch (no allocation allowed) ----------------
__device__ __half g_z16 [BS_TOT*HID];      // residual stream (post-LN2 / embed)
__device__ __half g_z116[BS_TOT*HID];      // post-LN1
__device__ __half g_qkv16[(long long)BS_TOT*QKVW];
__device__ __half g_att16[BS_TOT*HID];     // attention out & FFN out (fp16)
__device__ __half g_ffh16[BS_TOT*HID];
__device__ float  g_pool[NB*HID];
__device__ __half g_wqkv16[(long long)NLAYER*3*HID*HID];  // [L][3072][1024] transposed fp16
__device__ __half g_w1216 [(long long)NLAYER*2*HID*HID];  // [L][W1t|W2t] fp16
__device__ float  g_bqkv[NLAYER*QKVW];

// ============================ helpers ============================
__device__ __forceinline__ uint32_t smem_u32(const void* p) {
    return (uint32_t)__cvta_generic_to_shared(p);
}
__device__ __forceinline__ void cpa16(uint32_t dst, const void* src) {
    asm volatile("cp.async.cg.shared.global [%0], [%1], 16;" :: "r"(dst), "l"(src));
}
#define CPA_COMMIT() asm volatile("cp.async.commit_group;" ::: "memory")
template<int N> __device__ __forceinline__ void cpa_wait() {
    asm volatile("cp.async.wait_group %0;" :: "n"(N) : "memory");
}

__device__ __forceinline__ void mma_f16(float* c, const uint32_t* a, uint32_t b0, uint32_t b1) {
    asm volatile(
        "mma.sync.aligned.m16n8k16.row.col.f32.f16.f16.f32 "
        "{%0,%1,%2,%3}, {%4,%5,%6,%7}, {%8,%9}, {%0,%1,%2,%3};"
        : "+f"(c[0]), "+f"(c[1]), "+f"(c[2]), "+f"(c[3])
        : "r"(a[0]), "r"(a[1]), "r"(a[2]), "r"(a[3]), "r"(b0), "r"(b1));
}
__device__ __forceinline__ void ldsm_x4(uint32_t* r, uint32_t addr) {
    asm volatile("ldmatrix.sync.aligned.m8n8.x4.shared.b16 {%0,%1,%2,%3}, [%4];"
        : "=r"(r[0]), "=r"(r[1]), "=r"(r[2]), "=r"(r[3]) : "r"(addr));
}
__device__ __forceinline__ void ldsm_x4_t(uint32_t* r, uint32_t addr) {
    asm volatile("ldmatrix.sync.aligned.m8n8.x4.trans.shared.b16 {%0,%1,%2,%3}, [%4];"
        : "=r"(r[0]), "=r"(r[1]), "=r"(r[2]), "=r"(r[3]) : "r"(addr));
}

// ============================ weight transpose -> fp16 ============================
__global__ void transpose_h_kernel(const float* __restrict__ src, __half* __restrict__ dst,
                                   long long dstZ) {
    __shared__ float t[32][33];
    long long smoff = (long long)blockIdx.z * HID * HID;
    long long dmoff = (long long)blockIdx.z * dstZ;
    int x0 = blockIdx.x * 32, y0 = blockIdx.y * 32;
    int tx = threadIdx.x, ty = threadIdx.y;  // 32 x 8
#pragma unroll
    for (int j = 0; j < 32; j += 8)
        t[ty + j][tx] = src[smoff + (long long)(y0 + ty + j) * HID + x0 + tx];
    __syncthreads();
#pragma unroll
    for (int j = 0; j < 32; j += 8)
        dst[dmoff + (long long)(x0 + ty + j) * HID + y0 + tx] = __float2half(t[tx][ty + j]);
}

// bias pack: g_bqkv[l][t*1024+n]
__global__ void biaspack_kernel(const float* __restrict__ bq, const float* __restrict__ bk,
                                const float* __restrict__ bv) {
    int idx = blockIdx.x * 256 + threadIdx.x;
    if (idx >= NLAYER * QKVW) return;
    int l = idx / QKVW, r = idx % QKVW;
    int t = r >> 10, n = r & 1023;
    const float* src = (t == 0) ? bq : (t == 1) ? bk : bv;
    g_bqkv[idx] = src[l * HID + n];
}

// ============================ fp16 mma.sync GEMM (R12 proven shape) ============================
// C[M,N] = A[M,K] @ Wt^T + bias ; A fp16 [M,K] (lda=HID), Wt fp16 [N,K].
// BM=128, BN=128, BK=32 halves; 256 threads; warp grid 4x2, warp tile 32x64; 2 CTA/SM.
#define BKC   32
#define PADH  40
#define ABYTES (128 * PADH * 2)          // 10240
#define STAGEB (2 * ABYTES)              // 20480
#define NSTAGE 3
#define GEMM_SMEM (NSTAGE * STAGEB)      // 61440

__device__ __forceinline__ void gemm_load_stage(uint32_t sbase, int s, int kc, int tid,
                                                const __half* __restrict__ A,
                                                const __half* __restrict__ Bw,
                                                int row0, int col0) {
    uint32_t abase = sbase + s * STAGEB;
    uint32_t bbase = abase + ABYTES;
    const __half* Ag = A  + (long long)row0 * HID + kc * BKC;
    const __half* Bg = Bw + (long long)col0 * HID + kc * BKC;
#pragma unroll
    for (int j = 0; j < 2; j++) {
        int c = tid + j * 256;
        int r = c >> 2, q = c & 3;
        uint32_t so = (uint32_t)(r * PADH + q * 8) * 2;
        cpa16(abase + so, Ag + (long long)r * HID + q * 8);
        cpa16(bbase + so, Bg + (long long)r * HID + q * 8);
    }
}

// ACT: GELU on output (output always fp16)
template<int ACT>
__global__ __launch_bounds__(256, 2)
void gemm_h(const __half* __restrict__ A, const __half* __restrict__ Bw,
            const float* __restrict__ bias, __half* __restrict__ C, int ldC) {
    extern __shared__ __half smem[];
    const int tid = threadIdx.x;
    const int wid = tid >> 5, lane = tid & 31;
    const int wm = wid & 3, wn = wid >> 2;
    const int grp = lane >> 2, qid = lane & 3;
    const int row0 = blockIdx.y * 128;
    const int col0 = blockIdx.x * 128;
    uint32_t sbase = smem_u32(smem);

    float acc[2][8][4];
#pragma unroll
    for (int mf = 0; mf < 2; mf++)
#pragma unroll
        for (int nf = 0; nf < 8; nf++)
#pragma unroll
            for (int i = 0; i < 4; i++) acc[mf][nf][i] = 0.f;

    const int NKC = HID / BKC;   // 32

    gemm_load_stage(sbase, 0, 0, tid, A, Bw, row0, col0);
    CPA_COMMIT();
    gemm_load_stage(sbase, 1, 1, tid, A, Bw, row0, col0);
    CPA_COMMIT();

    const int a_row = wm * 32 + (lane & 15);
    const int a_k   = (lane >> 4) * 8;
    const int b_row = wn * 64 + (lane & 7);
    const int b_k   = (lane >> 3) * 8;

    for (int kc = 0; kc < NKC; kc++) {
        int s = kc % NSTAGE;
        if (kc + 2 < NKC)
            gemm_load_stage(sbase, (kc + 2) % NSTAGE, kc + 2, tid, A, Bw, row0, col0);
        CPA_COMMIT();
        cpa_wait<2>();
        __syncthreads();

        uint32_t sAu = sbase + s * STAGEB;
        uint32_t sBu = sAu + ABYTES;

        uint32_t afr[2][2][4];
#pragma unroll
        for (int mf = 0; mf < 2; mf++)
#pragma unroll
            for (int kk = 0; kk < 2; kk++)
                ldsm_x4(afr[mf][kk],
                        sAu + (uint32_t)((a_row + mf * 16) * PADH + kk * 16 + a_k) * 2);

#pragma unroll
        for (int nf = 0; nf < 8; nf++) {
            uint32_t bfr[4];
            ldsm_x4(bfr, sBu + (uint32_t)((b_row + nf * 8) * PADH + b_k) * 2);
            mma_f16(acc[0][nf], afr[0][0], bfr[0], bfr[1]);
            mma_f16(acc[1][nf], afr[1][0], bfr[0], bfr[1]);
            mma_f16(acc[0][nf], afr[0][1], bfr[2], bfr[3]);
            mma_f16(acc[1][nf], afr[1][1], bfr[2], bfr[3]);
        }
        __syncthreads();
    }

#pragma unroll
    for (int mf = 0; mf < 2; mf++) {
        int r0 = row0 + wm * 32 + mf * 16 + grp;
#pragma unroll
        for (int nf = 0; nf < 8; nf++) {
            int cg = col0 + wn * 64 + nf * 8 + 2 * qid;
            float bv0 = bias[cg], bv1 = bias[cg + 1];
            float v00 = acc[mf][nf][0] + bv0;
            float v01 = acc[mf][nf][1] + bv1;
            float v10 = acc[mf][nf][2] + bv0;
            float v11 = acc[mf][nf][3] + bv1;
            if (ACT) {
                v00 = 0.5f * v00 * (1.0f + erff(v00 * 0.70710678118654752f));
                v01 = 0.5f * v01 * (1.0f + erff(v01 * 0.70710678118654752f));
                v10 = 0.5f * v10 * (1.0f + erff(v10 * 0.70710678118654752f));
                v11 = 0.5f * v11 * (1.0f + erff(v11 * 0.70710678118654752f));
            }
            *(__half2*)&C[(long long)r0 * ldC + cg]       = __floats2half2_rn(v00, v01);
            *(__half2*)&C[(long long)(r0 + 8) * ldC + cg] = __floats2half2_rn(v10, v11);
        }
    }
}

// ============================ tensor-core flash attention (flash-v2) ============================
#define PADH2   72
#define QH_OFF  0
#define KH_OFF  (128 * PADH2 * 2)           // 18432
#define VH_OFF  (KH_OFF + 240 * PADH2 * 2)  // 52992
#define FA2_SMEM (VH_OFF + 240 * PADH2 * 2) // 87552

__global__ __launch_bounds__(256, 2)
void flash_attn2(const __half* __restrict__ qkv, const int* __restrict__ lengths,
                 __half* __restrict__ att) {
    extern __shared__ char fsm[];
    const int bh = blockIdx.x;
    const int half = blockIdx.y;
    const int b = bh >> 4, h = bh & 15;
    const int tid = threadIdx.x;
    const int w = tid >> 5, lane = tid & 31;
    const int grp = lane >> 2, qid = lane & 3;
    const int rbase = half * 128;
    const int len = lengths[b];
    const int kneed = half ? 240 : 128;

    const __half* base = qkv + (long long)b * SEQ * QKVW + h * DHEAD;

    {
        const int nQ = 128 * 8, nK = kneed * 8;
        for (int i = tid; i < nQ + 2 * nK; i += 256) {
            uint4 val = make_uint4(0, 0, 0, 0);
            char* dst;
            if (i < nQ) {
                int r = i >> 3, c = i & 7;
                int s = rbase + r;
                if (s < SEQ) val = *(const uint4*)(base + (long long)s * QKVW + c * 8);
                dst = fsm + QH_OFF + (r * PADH2 + c * 8) * 2;
            } else if (i < nQ + nK) {
                int j = i - nQ; int r = j >> 3, c = j & 7;
                val = *(const uint4*)(base + (long long)r * QKVW + 1024 + c * 8);
                dst = fsm + KH_OFF + (r * PADH2 + c * 8) * 2;
            } else {
                int j = i - nQ - nK; int r = j >> 3, c = j & 7;
                val = *(const uint4*)(base + (long long)r * QKVW + 2048 + c * 8);
                dst = fsm + VH_OFF + (r * PADH2 + c * 8) * 2;
            }
            *(uint4*)dst = val;
        }
    }
    __syncthreads();

    if (rbase + w * 16 >= SEQ) return;

    const uint32_t sb = smem_u32(fsm);
    const uint32_t QhU = sb + QH_OFF, KhU = sb + KH_OFF, VhU = sb + VH_OFF;

    const int row0g = rbase + w * 16 + grp;
    const int row1g = row0g + 8;
    const int nch = min(8 * half + w + 1, 15);

    uint32_t qf[4][4];
#pragma unroll
    for (int dk = 0; dk < 4; dk++)
        ldsm_x4(qf[dk], QhU + (uint32_t)((w * 16 + (lane & 15)) * PADH2
                                         + dk * 16 + ((lane >> 4) << 3)) * 2);

    float m0 = -1e30f, m1 = -1e30f, l0 = 0.f, l1 = 0.f;
    float acc[8][4];
#pragma unroll
    for (int nf = 0; nf < 8; nf++)
#pragma unroll
        for (int i = 0; i < 4; i++) acc[nf][i] = 0.f;

    const float sc = 1.0f / 32.0f;

    for (int kc = 0; kc < nch; kc++) {
        float S[2][4];
#pragma unroll
        for (int ng = 0; ng < 2; ng++)
#pragma unroll
            for (int i = 0; i < 4; i++) S[ng][i] = 0.f;

#pragma unroll
        for (int dg2 = 0; dg2 < 2; dg2++) {
#pragma unroll
            for (int ng = 0; ng < 2; ng++) {
                uint32_t kb[4];
                ldsm_x4(kb, KhU + (uint32_t)((kc * 16 + ng * 8 + (lane & 7)) * PADH2
                                             + dg2 * 32 + ((lane >> 3) << 3)) * 2);
                mma_f16(S[ng], qf[dg2 * 2 + 0], kb[0], kb[1]);
                mma_f16(S[ng], qf[dg2 * 2 + 1], kb[2], kb[3]);
            }
        }

        float s_[2][4];
#pragma unroll
        for (int ng = 0; ng < 2; ng++) {
            int colb = kc * 16 + ng * 8 + 2 * qid;
            s_[ng][0] = (colb     <= row0g) ? S[ng][0] * sc : -1e30f;
            s_[ng][1] = (colb + 1 <= row0g) ? S[ng][1] * sc : -1e30f;
            s_[ng][2] = (colb     <= row1g) ? S[ng][2] * sc : -1e30f;
            s_[ng][3] = (colb + 1 <= row1g) ? S[ng][3] * sc : -1e30f;
        }

        float mc0 = fmaxf(fmaxf(s_[0][0], s_[0][1]), fmaxf(s_[1][0], s_[1][1]));
        float mc1 = fmaxf(fmaxf(s_[0][2], s_[0][3]), fmaxf(s_[1][2], s_[1][3]));
        mc0 = fmaxf(mc0, __shfl_xor_sync(0xffffffff, mc0, 1));
        mc0 = fmaxf(mc0, __shfl_xor_sync(0xffffffff, mc0, 2));
        mc1 = fmaxf(mc1, __shfl_xor_sync(0xffffffff, mc1, 1));
        mc1 = fmaxf(mc1, __shfl_xor_sync(0xffffffff, mc1, 2));
        float m0n = fmaxf(m0, mc0), m1n = fmaxf(m1, mc1);
        float sf0 = __expf(m0 - m0n), sf1 = __expf(m1 - m1n);

        float p[2][4];
#pragma unroll
        for (int ng = 0; ng < 2; ng++) {
            p[ng][0] = __expf(s_[ng][0] - m0n);
            p[ng][1] = __expf(s_[ng][1] - m0n);
            p[ng][2] = __expf(s_[ng][2] - m1n);
            p[ng][3] = __expf(s_[ng][3] - m1n);
        }
        float rs0 = p[0][0] + p[0][1] + p[1][0] + p[1][1];
        float rs1 = p[0][2] + p[0][3] + p[1][2] + p[1][3];
        rs0 += __shfl_xor_sync(0xffffffff, rs0, 1);
        rs0 += __shfl_xor_sync(0xffffffff, rs0, 2);
        rs1 += __shfl_xor_sync(0xffffffff, rs1, 1);
        rs1 += __shfl_xor_sync(0xffffffff, rs1, 2);
        l0 = l0 * sf0 + rs0;  m0 = m0n;
        l1 = l1 * sf1 + rs1;  m1 = m1n;

#pragma unroll
        for (int nf = 0; nf < 8; nf++) {
            acc[nf][0] *= sf0; acc[nf][1] *= sf0;
            acc[nf][2] *= sf1; acc[nf][3] *= sf1;
        }

        uint32_t ap[4];
        {
            __half2 h0 = __floats2half2_rn(p[0][0], p[0][1]);
            __half2 h1 = __floats2half2_rn(p[0][2], p[0][3]);
            __half2 h2 = __floats2half2_rn(p[1][0], p[1][1]);
            __half2 h3 = __floats2half2_rn(p[1][2], p[1][3]);
            ap[0] = *(uint32_t*)&h0;
            ap[1] = *(uint32_t*)&h1;
            ap[2] = *(uint32_t*)&h2;
            ap[3] = *(uint32_t*)&h3;
        }

#pragma unroll
        for (int dg = 0; dg < 4; dg++) {
            uint32_t vb[4];
            ldsm_x4_t(vb, VhU + (uint32_t)((kc * 16 + (lane & 15)) * PADH2
                                           + dg * 16 + ((lane >> 4) << 3)) * 2);
            mma_f16(acc[2 * dg],     ap, vb[0], vb[1]);
            mma_f16(acc[2 * dg + 1], ap, vb[2], vb[3]);
        }
    }

    float inv0 = (row0g < len) ? (1.0f / l0) : 0.0f;
    float inv1 = (row1g < len) ? (1.0f / l1) : 0.0f;
    __half* ob0 = att + (long long)(b * SEQ + row0g) * HID + h * DHEAD;
    __half* ob1 = att + (long long)(b * SEQ + row1g) * HID + h * DHEAD;
#pragma unroll
    for (int nf = 0; nf < 8; nf++) {
        int col = (nf >> 1) * 16 + (nf & 1) * 8 + 2 * qid;
        *(__half2*)&ob0[col] = __floats2half2_rn(acc[nf][0] * inv0, acc[nf][1] * inv0);
        *(__half2*)&ob1[col] = __floats2half2_rn(acc[nf][2] * inv1, acc[nf][3] * inv1);
    }
}

// ---------------- embedding: argmax + gather + posenc (fp16 out) ----------------
__global__ void embed_kernel(const float* __restrict__ x,
                             const float* __restrict__ w_emb,
                             const float* __restrict__ p_emb,
                             const int*   __restrict__ lengths) {
    int bs = blockIdx.x;
    int b = bs / SEQ, s = bs % SEQ;
    __shared__ int s_tok;
    int tid = threadIdx.x;
    if (tid < 32) {
        const float* xp = x + (long long)bs * NVOCAB;
        float bv = -1e30f; int bi = 0;
        for (int c = tid; c < NVOCAB; c += 32) {
            float v = xp[c];
            if (v > bv) { bv = v; bi = c; }
        }
        for (int off = 16; off > 0; off >>= 1) {
            float ov = __shfl_down_sync(0xffffffff, bv, off);
            int   oi = __shfl_down_sync(0xffffffff, bi, off);
            if (ov > bv || (ov == bv && oi < bi)) { bv = ov; bi = oi; }
        }
        if (tid == 0) s_tok = bi;
    }
    __syncthreads();
    int tok = s_tok;
    float valid = (s < lengths[b]) ? 1.0f : 0.0f;
    const float* we = w_emb + (long long)tok * HID;
    const float* pe = p_emb + (long long)s * HID;
    __half* zph = g_z16 + (long long)bs * HID;
    for (int h = tid; h < HID; h += blockDim.x) {
        float v = we[h] * valid + pe[h];
        zph[h] = __float2half(v);
    }
}

// ---------------- residual add + LayerNorm (fp16 in, fp16 out; fp32 stats) ----------------
__global__ void add_ln_kernel(const __half* __restrict__ a, const __half* __restrict__ r,
                              const float* __restrict__ sc, const float* __restrict__ bi,
                              __half* __restrict__ out) {
    int row = blockIdx.x;
    int tid = threadIdx.x;
    const __half* ap = a + (long long)row * HID;
    const __half* rp = r + (long long)row * HID;
    int h0 = tid * 4;
    // 4 contiguous halves per thread -> 256B per warp access
    uint2 araw = *(const uint2*)(ap + h0);
    uint2 rraw = *(const uint2*)(rp + h0);
    const __half2* a2 = (const __half2*)&araw;
    const __half2* r2 = (const __half2*)&rraw;
    float v[4];
    {
        float2 f0 = __half22float2(a2[0]), f1 = __half22float2(a2[1]);
        float2 g0 = __half22float2(r2[0]), g1 = __half22float2(r2[1]);
        v[0] = f0.x + g0.x; v[1] = f0.y + g0.y;
        v[2] = f1.x + g1.x; v[3] = f1.y + g1.y;
    }
    float s = v[0] + v[1] + v[2] + v[3];
    float sq = v[0]*v[0] + v[1]*v[1] + v[2]*v[2] + v[3]*v[3];

    __shared__ float red1[8], red2[8];
    for (int off = 16; off > 0; off >>= 1) {
        s  += __shfl_xor_sync(0xffffffff, s,  off);
        sq += __shfl_xor_sync(0xffffffff, sq, off);
    }
    int warp = tid >> 5, lane = tid & 31;
    if (lane == 0) { red1[warp] = s; red2[warp] = sq; }
    __syncthreads();
    if (warp == 0) {
        s  = (lane < 8) ? red1[lane] : 0.f;
        sq = (lane < 8) ? red2[lane] : 0.f;
        for (int off = 4; off > 0; off >>= 1) {
            s  += __shfl_xor_sync(0xffffffff, s,  off);
            sq += __shfl_xor_sync(0xffffffff, sq, off);
        }
        if (lane == 0) { red1[0] = s; red2[0] = sq; }
    }
    __syncthreads();
    float mean = red1[0] * (1.0f / HID);
    float var  = red2[0] * (1.0f / HID) - mean * mean;
    float rstd = rsqrtf(var + 1e-5f);

    float4 scv = *(const float4*)(sc + h0);
    float4 biv = *(const float4*)(bi + h0);
    float o0 = (v[0] - mean) * rstd * scv.x + biv.x;
    float o1 = (v[1] - mean) * rstd * scv.y + biv.y;
    float o2 = (v[2] - mean) * rstd * scv.z + biv.z;
    float o3 = (v[3] - mean) * rstd * scv.w + biv.w;
    uint2 oraw;
    __half2* o2p = (__half2*)&oraw;
    o2p[0] = __floats2half2_rn(o0, o1);
    o2p[1] = __floats2half2_rn(o2, o3);
    *(uint2*)(out + (long long)row * HID + h0) = oraw;
}

// ---------------- mean-pool (fp16 in, fp32 accumulate) ----------------
__global__ void pool_kernel() {
    int b = blockIdx.y;
    int h = blockIdx.x * 256 + threadIdx.x;
    float s = 0.f;
    const __half* zp = g_z16 + (long long)b * SEQ * HID + h;
    for (int si = 0; si < SEQ; si++)
        s += __half2float(zp[(long long)si * HID]);
    g_pool[b * HID + h] = s * (1.0f / SEQ);
}

// ---------------- classifier head + softmax(4) ----------------
__global__ void head_kernel(const float* __restrict__ Wfc, const float* __restrict__ bfc,
                            float* __restrict__ out) {
    int b = blockIdx.x;
    int tid = threadIdx.x;
    float p[4] = {0.f, 0.f, 0.f, 0.f};
    const float* zp = g_pool + b * HID;
    for (int h = tid; h < HID; h += 256) {
        float zv = zp[h];
#pragma unroll
        for (int c = 0; c < 4; c++) p[c] += zv * Wfc[h*4 + c];
    }
    __shared__ float red[4][256];
#pragma unroll
    for (int c = 0; c < 4; c++) red[c][tid] = p[c];
    __syncthreads();
    for (int str = 128; str > 0; str >>= 1) {
        if (tid < str)
#pragma unroll
            for (int c = 0; c < 4; c++) red[c][tid] += red[c][tid + str];
        __syncthreads();
    }
    if (tid == 0) {
        float l[4];
        float m = -1e30f;
#pragma unroll
        for (int c = 0; c < 4; c++) { l[c] = red[c][0] + bfc[c]; m = fmaxf(m, l[c]); }
        float ssum = 0.f;
#pragma unroll
        for (int c = 0; c < 4; c++) { l[c] = __expf(l[c] - m); ssum += l[c]; }
        float inv = 1.0f / ssum;
#pragma unroll
        for (int c = 0; c < 4; c++) out[b*4 + c] = l[c] * inv;
    }
}

// ---------------- host orchestration ----------------
extern "C" void kernel_launch(void* const* d_in, const int* in_sizes, int n_in,
                              void* d_out, int out_size) {
    const float* x     = (const float*)d_in[0];
    const float* w_emb = (const float*)d_in[1];
    const float* p_emb = (const float*)d_in[2];
    const float* Wq    = (const float*)d_in[3];
    const float* bq    = (const float*)d_in[4];
    const float* Wk    = (const float*)d_in[5];
    const float* bk    = (const float*)d_in[6];
    const float* Wv    = (const float*)d_in[7];
    const float* bv    = (const float*)d_in[8];
    const float* W1    = (const float*)d_in[9];
    const float* b1    = (const float*)d_in[10];
    const float* W2    = (const float*)d_in[11];
    const float* b2    = (const float*)d_in[12];
    const float* ln1_s = (const float*)d_in[13];
    const float* ln1_b = (const float*)d_in[14];
    const float* ln2_s = (const float*)d_in[15];
    const float* ln2_b = (const float*)d_in[16];
    const float* Wfc   = (const float*)d_in[17];
    const float* bfc   = (const float*)d_in[18];
    const int*   lengths = (const int*)d_in[19];
    float* out = (float*)d_out;

    float *pbqkv;
    __half *pz16, *pz116, *pffh16, *pwqkv16, *pw1216, *pqkv16, *patt16;
    cudaGetSymbolAddress((void**)&pz16,   g_z16);
    cudaGetSymbolAddress((void**)&pz116,  g_z116);
    cudaGetSymbolAddress((void**)&pqkv16, g_qkv16);
    cudaGetSymbolAddress((void**)&patt16, g_att16);
    cudaGetSymbolAddress((void**)&pffh16, g_ffh16);
    cudaGetSymbolAddress((void**)&pwqkv16,g_wqkv16);
    cudaGetSymbolAddress((void**)&pw1216, g_w1216);
    cudaGetSymbolAddress((void**)&pbqkv,  g_bqkv);

    cudaFuncSetAttribute((const void*)gemm_h<0>, cudaFuncAttributeMaxDynamicSharedMemorySize, GEMM_SMEM);
    cudaFuncSetAttribute((const void*)gemm_h<1>, cudaFuncAttributeMaxDynamicSharedMemorySize, GEMM_SMEM);
    cudaFuncSetAttribute((const void*)flash_attn2, cudaFuncAttributeMaxDynamicSharedMemorySize, FA2_SMEM);

    const long long MAT = (long long)HID * HID;

    dim3 tgrid(HID/32, HID/32, NLAYER);
    dim3 tblk(32, 8);
    transpose_h_kernel<<<tgrid, tblk>>>(Wq, pwqkv16 + 0*MAT, 3*MAT);
    transpose_h_kernel<<<tgrid, tblk>>>(Wk, pwqkv16 + 1*MAT, 3*MAT);
    transpose_h_kernel<<<tgrid, tblk>>>(Wv, pwqkv16 + 2*MAT, 3*MAT);
    transpose_h_kernel<<<tgrid, tblk>>>(W1, pw1216  + 0*MAT, 2*MAT);
    transpose_h_kernel<<<tgrid, tblk>>>(W2, pw1216  + 1*MAT, 2*MAT);
    biaspack_kernel<<<(NLAYER*QKVW + 255)/256, 256>>>(bq, bk, bv);

    embed_kernel<<<BS_TOT, 256>>>(x, w_emb, p_emb, lengths);

    dim3 qkv_grid(QKVW/128, BS_TOT/128);   // (24, 60)
    dim3 ff_grid(HID/128, BS_TOT/128);     // (8, 60)
    dim3 fa_grid(NB*NHEAD, 2);             // (512, 2)

    for (int i = 0; i < NLAYER; i++) {
        long long bOff = (long long)i * HID;
        gemm_h<0><<<qkv_grid, 256, GEMM_SMEM>>>(pz16, pwqkv16 + (long long)i*3*MAT,
                                                pbqkv + (long long)i*QKVW, pqkv16, QKVW);
        flash_attn2<<<fa_grid, 256, FA2_SMEM>>>(pqkv16, lengths, patt16);
        add_ln_kernel<<<BS_TOT, 256>>>(patt16, pz16, ln1_s + bOff, ln1_b + bOff, pz116);
        gemm_h<1><<<ff_grid, 256, GEMM_SMEM>>>(pz116, pw1216 + (long long)i*2*MAT,
                                               b1 + bOff, pffh16, HID);
        gemm_h<0><<<ff_grid, 256, GEMM_SMEM>>>(pffh16, pw1216 + (long long)i*2*MAT + MAT,
                                               b2 + bOff, patt16, HID);
        add_ln_kernel<<<BS_TOT, 256>>>(patt16, pz116, ln2_s + bOff, ln2_b + bOff, pz16);
    }

    pool_kernel<<<dim3(HID/256, NB), 256>>>();
    head_kernel<<<NB, 256>>>(Wfc, bfc, out);
}

// round 16
// speedup vs baseline: 1.1376x; 1.0084x over previous
#include <cuda_runtime.h>
#include <cuda_fp16.h>
#include <math.h>
#include <cstdint>

#define NB     32
#define SEQ    240
#define HID    1024
#define NLAYER 8
#define NHEAD  16
#define DHEAD  64
#define NVOCAB 48
#define BS_TOT (NB*SEQ)   // 7680
#define QKVW   3072

// ---------------- device scratch (no allocation allowed) ----------------
__device__ __half g_z16 [BS_TOT*HID];      // residual stream (post-LN2 / embed)
__device__ __half g_z116[BS_TOT*HID];      // post-LN1
__device__ __half g_qkv16[(long long)BS_TOT*QKVW];
__device__ __half g_att16[BS_TOT*HID];     // attention out & FFN out (fp16)
__device__ __half g_ffh16[BS_TOT*HID];
__device__ float  g_pool[NB*HID];
__device__ __half g_wqkv16[(long long)NLAYER*3*HID*HID];  // [L][3072][1024] transposed fp16
__device__ __half g_w1216 [(long long)NLAYER*2*HID*HID];  // [L][W1t|W2t] fp16
__device__ float  g_bqkv[NLAYER*QKVW];

// ============================ helpers ============================
__device__ __forceinline__ uint32_t smem_u32(const void* p) {
    return (uint32_t)__cvta_generic_to_shared(p);
}
__device__ __forceinline__ void cpa16(uint32_t dst, const void* src) {
    asm volatile("cp.async.cg.shared.global [%0], [%1], 16;" :: "r"(dst), "l"(src));
}
#define CPA_COMMIT() asm volatile("cp.async.commit_group;" ::: "memory")
template<int N> __device__ __forceinline__ void cpa_wait() {
    asm volatile("cp.async.wait_group %0;" :: "n"(N) : "memory");
}

__device__ __forceinline__ void mma_f16(float* c, const uint32_t* a, uint32_t b0, uint32_t b1) {
    asm volatile(
        "mma.sync.aligned.m16n8k16.row.col.f32.f16.f16.f32 "
        "{%0,%1,%2,%3}, {%4,%5,%6,%7}, {%8,%9}, {%0,%1,%2,%3};"
        : "+f"(c[0]), "+f"(c[1]), "+f"(c[2]), "+f"(c[3])
        : "r"(a[0]), "r"(a[1]), "r"(a[2]), "r"(a[3]), "r"(b0), "r"(b1));
}
__device__ __forceinline__ void ldsm_x4(uint32_t* r, uint32_t addr) {
    asm volatile("ldmatrix.sync.aligned.m8n8.x4.shared.b16 {%0,%1,%2,%3}, [%4];"
        : "=r"(r[0]), "=r"(r[1]), "=r"(r[2]), "=r"(r[3]) : "r"(addr));
}
__device__ __forceinline__ void ldsm_x4_t(uint32_t* r, uint32_t addr) {
    asm volatile("ldmatrix.sync.aligned.m8n8.x4.trans.shared.b16 {%0,%1,%2,%3}, [%4];"
        : "=r"(r[0]), "=r"(r[1]), "=r"(r[2]), "=r"(r[3]) : "r"(addr));
}

// ============================ merged weight transpose -> fp16 ============================
// grid.z = 5*NLAYER; z -> (matrix type, layer). dst[n*HID+k] = (half)src[k*HID+n].
__global__ void transpose_all_kernel(const float* __restrict__ Wq, const float* __restrict__ Wk,
                                     const float* __restrict__ Wv, const float* __restrict__ W1,
                                     const float* __restrict__ W2,
                                     __half* __restrict__ wqkv, __half* __restrict__ w12) {
    __shared__ float t[32][33];
    const long long MAT = (long long)HID * HID;
    int z = blockIdx.z;
    int ty_ = z / NLAYER;            // 0..4
    int l  = z % NLAYER;
    const float* src =
        (ty_ == 0 ? Wq : ty_ == 1 ? Wk : ty_ == 2 ? Wv : ty_ == 3 ? W1 : W2) + (long long)l * MAT;
    __half* dst = (ty_ < 3) ? (wqkv + (long long)l * 3 * MAT + (long long)ty_ * MAT)
                            : (w12  + (long long)l * 2 * MAT + (long long)(ty_ - 3) * MAT);
    int x0 = blockIdx.x * 32, y0 = blockIdx.y * 32;
    int tx = threadIdx.x, ty = threadIdx.y;  // 32 x 8
#pragma unroll
    for (int j = 0; j < 32; j += 8)
        t[ty + j][tx] = src[(long long)(y0 + ty + j) * HID + x0 + tx];
    __syncthreads();
#pragma unroll
    for (int j = 0; j < 32; j += 8)
        dst[(long long)(x0 + ty + j) * HID + y0 + tx] = __float2half(t[tx][ty + j]);
}

// bias pack: g_bqkv[l][t*1024+n]
__global__ void biaspack_kernel(const float* __restrict__ bq, const float* __restrict__ bk,
                                const float* __restrict__ bv) {
    int idx = blockIdx.x * 256 + threadIdx.x;
    if (idx >= NLAYER * QKVW) return;
    int l = idx / QKVW, r = idx % QKVW;
    int t = r >> 10, n = r & 1023;
    const float* src = (t == 0) ? bq : (t == 1) ? bk : bv;
    g_bqkv[idx] = src[l * HID + n];
}

// ============================ fp16 mma.sync GEMM (R12 proven shape, FROZEN) ============================
#define BKC   32
#define PADH  40
#define ABYTES (128 * PADH * 2)          // 10240
#define STAGEB (2 * ABYTES)              // 20480
#define NSTAGE 3
#define GEMM_SMEM (NSTAGE * STAGEB)      // 61440

__device__ __forceinline__ void gemm_load_stage(uint32_t sbase, int s, int kc, int tid,
                                                const __half* __restrict__ A,
                                                const __half* __restrict__ Bw,
                                                int row0, int col0) {
    uint32_t abase = sbase + s * STAGEB;
    uint32_t bbase = abase + ABYTES;
    const __half* Ag = A  + (long long)row0 * HID + kc * BKC;
    const __half* Bg = Bw + (long long)col0 * HID + kc * BKC;
#pragma unroll
    for (int j = 0; j < 2; j++) {
        int c = tid + j * 256;
        int r = c >> 2, q = c & 3;
        uint32_t so = (uint32_t)(r * PADH + q * 8) * 2;
        cpa16(abase + so, Ag + (long long)r * HID + q * 8);
        cpa16(bbase + so, Bg + (long long)r * HID + q * 8);
    }
}

// ACT: GELU on output (output always fp16)
template<int ACT>
__global__ __launch_bounds__(256, 2)
void gemm_h(const __half* __restrict__ A, const __half* __restrict__ Bw,
            const float* __restrict__ bias, __half* __restrict__ C, int ldC) {
    extern __shared__ __half smem[];
    const int tid = threadIdx.x;
    const int wid = tid >> 5, lane = tid & 31;
    const int wm = wid & 3, wn = wid >> 2;
    const int grp = lane >> 2, qid = lane & 3;
    const int row0 = blockIdx.y * 128;
    const int col0 = blockIdx.x * 128;
    uint32_t sbase = smem_u32(smem);

    float acc[2][8][4];
#pragma unroll
    for (int mf = 0; mf < 2; mf++)
#pragma unroll
        for (int nf = 0; nf < 8; nf++)
#pragma unroll
            for (int i = 0; i < 4; i++) acc[mf][nf][i] = 0.f;

    const int NKC = HID / BKC;   // 32

    gemm_load_stage(sbase, 0, 0, tid, A, Bw, row0, col0);
    CPA_COMMIT();
    gemm_load_stage(sbase, 1, 1, tid, A, Bw, row0, col0);
    CPA_COMMIT();

    const int a_row = wm * 32 + (lane & 15);
    const int a_k   = (lane >> 4) * 8;
    const int b_row = wn * 64 + (lane & 7);
    const int b_k   = (lane >> 3) * 8;

    for (int kc = 0; kc < NKC; kc++) {
        int s = kc % NSTAGE;
        if (kc + 2 < NKC)
            gemm_load_stage(sbase, (kc + 2) % NSTAGE, kc + 2, tid, A, Bw, row0, col0);
        CPA_COMMIT();
        cpa_wait<2>();
        __syncthreads();

        uint32_t sAu = sbase + s * STAGEB;
        uint32_t sBu = sAu + ABYTES;

        uint32_t afr[2][2][4];
#pragma unroll
        for (int mf = 0; mf < 2; mf++)
#pragma unroll
            for (int kk = 0; kk < 2; kk++)
                ldsm_x4(afr[mf][kk],
                        sAu + (uint32_t)((a_row + mf * 16) * PADH + kk * 16 + a_k) * 2);

#pragma unroll
        for (int nf = 0; nf < 8; nf++) {
            uint32_t bfr[4];
            ldsm_x4(bfr, sBu + (uint32_t)((b_row + nf * 8) * PADH + b_k) * 2);
            mma_f16(acc[0][nf], afr[0][0], bfr[0], bfr[1]);
            mma_f16(acc[1][nf], afr[1][0], bfr[0], bfr[1]);
            mma_f16(acc[0][nf], afr[0][1], bfr[2], bfr[3]);
            mma_f16(acc[1][nf], afr[1][1], bfr[2], bfr[3]);
        }
        __syncthreads();
    }

#pragma unroll
    for (int mf = 0; mf < 2; mf++) {
        int r0 = row0 + wm * 32 + mf * 16 + grp;
#pragma unroll
        for (int nf = 0; nf < 8; nf++) {
            int cg = col0 + wn * 64 + nf * 8 + 2 * qid;
            float bv0 = bias[cg], bv1 = bias[cg + 1];
            float v00 = acc[mf][nf][0] + bv0;
            float v01 = acc[mf][nf][1] + bv1;
            float v10 = acc[mf][nf][2] + bv0;
            float v11 = acc[mf][nf][3] + bv1;
            if (ACT) {
                v00 = 0.5f * v00 * (1.0f + erff(v00 * 0.70710678118654752f));
                v01 = 0.5f * v01 * (1.0f + erff(v01 * 0.70710678118654752f));
                v10 = 0.5f * v10 * (1.0f + erff(v10 * 0.70710678118654752f));
                v11 = 0.5f * v11 * (1.0f + erff(v11 * 0.70710678118654752f));
            }
            *(__half2*)&C[(long long)r0 * ldC + cg]       = __floats2half2_rn(v00, v01);
            *(__half2*)&C[(long long)(r0 + 8) * ldC + cg] = __floats2half2_rn(v10, v11);
        }
    }
}

// ============================ tensor-core flash attention (flash-v2) ============================
#define PADH2   72
#define QH_OFF  0
#define KH_OFF  (128 * PADH2 * 2)           // 18432
#define VH_OFF  (KH_OFF + 240 * PADH2 * 2)  // 52992
#define FA2_SMEM (VH_OFF + 240 * PADH2 * 2) // 87552

__global__ __launch_bounds__(256, 2)
void flash_attn2(const __half* __restrict__ qkv, const int* __restrict__ lengths,
                 __half* __restrict__ att) {
    extern __shared__ char fsm[];
    const int bh = blockIdx.x;
    const int half = blockIdx.y;
    const int b = bh >> 4, h = bh & 15;
    const int tid = threadIdx.x;
    const int w = tid >> 5, lane = tid & 31;
    const int grp = lane >> 2, qid = lane & 3;
    const int rbase = half * 128;
    const int len = lengths[b];
    const int kneed = half ? 240 : 128;

    const __half* base = qkv + (long long)b * SEQ * QKVW + h * DHEAD;

    {
        const int nQ = 128 * 8, nK = kneed * 8;
        for (int i = tid; i < nQ + 2 * nK; i += 256) {
            uint4 val = make_uint4(0, 0, 0, 0);
            char* dst;
            if (i < nQ) {
                int r = i >> 3, c = i & 7;
                int s = rbase + r;
                if (s < SEQ) val = *(const uint4*)(base + (long long)s * QKVW + c * 8);
                dst = fsm + QH_OFF + (r * PADH2 + c * 8) * 2;
            } else if (i < nQ + nK) {
                int j = i - nQ; int r = j >> 3, c = j & 7;
                val = *(const uint4*)(base + (long long)r * QKVW + 1024 + c * 8);
                dst = fsm + KH_OFF + (r * PADH2 + c * 8) * 2;
            } else {
                int j = i - nQ - nK; int r = j >> 3, c = j & 7;
                val = *(const uint4*)(base + (long long)r * QKVW + 2048 + c * 8);
                dst = fsm + VH_OFF + (r * PADH2 + c * 8) * 2;
            }
            *(uint4*)dst = val;
        }
    }
    __syncthreads();

    if (rbase + w * 16 >= SEQ) return;

    const uint32_t sb = smem_u32(fsm);
    const uint32_t QhU = sb + QH_OFF, KhU = sb + KH_OFF, VhU = sb + VH_OFF;

    const int row0g = rbase + w * 16 + grp;
    const int row1g = row0g + 8;
    const int nch = min(8 * half + w + 1, 15);

    uint32_t qf[4][4];
#pragma unroll
    for (int dk = 0; dk < 4; dk++)
        ldsm_x4(qf[dk], QhU + (uint32_t)((w * 16 + (lane & 15)) * PADH2
                                         + dk * 16 + ((lane >> 4) << 3)) * 2);

    float m0 = -1e30f, m1 = -1e30f, l0 = 0.f, l1 = 0.f;
    float acc[8][4];
#pragma unroll
    for (int nf = 0; nf < 8; nf++)
#pragma unroll
        for (int i = 0; i < 4; i++) acc[nf][i] = 0.f;

    const float sc = 1.0f / 32.0f;

    for (int kc = 0; kc < nch; kc++) {
        float S[2][4];
#pragma unroll
        for (int ng = 0; ng < 2; ng++)
#pragma unroll
            for (int i = 0; i < 4; i++) S[ng][i] = 0.f;

#pragma unroll
        for (int dg2 = 0; dg2 < 2; dg2++) {
#pragma unroll
            for (int ng = 0; ng < 2; ng++) {
                uint32_t kb[4];
                ldsm_x4(kb, KhU + (uint32_t)((kc * 16 + ng * 8 + (lane & 7)) * PADH2
                                             + dg2 * 32 + ((lane >> 3) << 3)) * 2);
                mma_f16(S[ng], qf[dg2 * 2 + 0], kb[0], kb[1]);
                mma_f16(S[ng], qf[dg2 * 2 + 1], kb[2], kb[3]);
            }
        }

        float s_[2][4];
#pragma unroll
        for (int ng = 0; ng < 2; ng++) {
            int colb = kc * 16 + ng * 8 + 2 * qid;
            s_[ng][0] = (colb     <= row0g) ? S[ng][0] * sc : -1e30f;
            s_[ng][1] = (colb + 1 <= row0g) ? S[ng][1] * sc : -1e30f;
            s_[ng][2] = (colb     <= row1g) ? S[ng][2] * sc : -1e30f;
            s_[ng][3] = (colb + 1 <= row1g) ? S[ng][3] * sc : -1e30f;
        }

        float mc0 = fmaxf(fmaxf(s_[0][0], s_[0][1]), fmaxf(s_[1][0], s_[1][1]));
        float mc1 = fmaxf(fmaxf(s_[0][2], s_[0][3]), fmaxf(s_[1][2], s_[1][3]));
        mc0 = fmaxf(mc0, __shfl_xor_sync(0xffffffff, mc0, 1));
        mc0 = fmaxf(mc0, __shfl_xor_sync(0xffffffff, mc0, 2));
        mc1 = fmaxf(mc1, __shfl_xor_sync(0xffffffff, mc1, 1));
        mc1 = fmaxf(mc1, __shfl_xor_sync(0xffffffff, mc1, 2));
        float m0n = fmaxf(m0, mc0), m1n = fmaxf(m1, mc1);
        float sf0 = __expf(m0 - m0n), sf1 = __expf(m1 - m1n);

        float p[2][4];
#pragma unroll
        for (int ng = 0; ng < 2; ng++) {
            p[ng][0] = __expf(s_[ng][0] - m0n);
            p[ng][1] = __expf(s_[ng][1] - m0n);
            p[ng][2] = __expf(s_[ng][2] - m1n);
            p[ng][3] = __expf(s_[ng][3] - m1n);
        }
        float rs0 = p[0][0] + p[0][1] + p[1][0] + p[1][1];
        float rs1 = p[0][2] + p[0][3] + p[1][2] + p[1][3];
        rs0 += __shfl_xor_sync(0xffffffff, rs0, 1);
        rs0 += __shfl_xor_sync(0xffffffff, rs0, 2);
        rs1 += __shfl_xor_sync(0xffffffff, rs1, 1);
        rs1 += __shfl_xor_sync(0xffffffff, rs1, 2);
        l0 = l0 * sf0 + rs0;  m0 = m0n;
        l1 = l1 * sf1 + rs1;  m1 = m1n;

#pragma unroll
        for (int nf = 0; nf < 8; nf++) {
            acc[nf][0] *= sf0; acc[nf][1] *= sf0;
            acc[nf][2] *= sf1; acc[nf][3] *= sf1;
        }

        uint32_t ap[4];
        {
            __half2 h0 = __floats2half2_rn(p[0][0], p[0][1]);
            __half2 h1 = __floats2half2_rn(p[0][2], p[0][3]);
            __half2 h2 = __floats2half2_rn(p[1][0], p[1][1]);
            __half2 h3 = __floats2half2_rn(p[1][2], p[1][3]);
            ap[0] = *(uint32_t*)&h0;
            ap[1] = *(uint32_t*)&h1;
            ap[2] = *(uint32_t*)&h2;
            ap[3] = *(uint32_t*)&h3;
        }

#pragma unroll
        for (int dg = 0; dg < 4; dg++) {
            uint32_t vb[4];
            ldsm_x4_t(vb, VhU + (uint32_t)((kc * 16 + (lane & 15)) * PADH2
                                           + dg * 16 + ((lane >> 4) << 3)) * 2);
            mma_f16(acc[2 * dg],     ap, vb[0], vb[1]);
            mma_f16(acc[2 * dg + 1], ap, vb[2], vb[3]);
        }
    }

    float inv0 = (row0g < len) ? (1.0f / l0) : 0.0f;
    float inv1 = (row1g < len) ? (1.0f / l1) : 0.0f;
    __half* ob0 = att + (long long)(b * SEQ + row0g) * HID + h * DHEAD;
    __half* ob1 = att + (long long)(b * SEQ + row1g) * HID + h * DHEAD;
#pragma unroll
    for (int nf = 0; nf < 8; nf++) {
        int col = (nf >> 1) * 16 + (nf & 1) * 8 + 2 * qid;
        *(__half2*)&ob0[col] = __floats2half2_rn(acc[nf][0] * inv0, acc[nf][1] * inv0);
        *(__half2*)&ob1[col] = __floats2half2_rn(acc[nf][2] * inv1, acc[nf][3] * inv1);
    }
}

// ---------------- embedding: argmax + gather + posenc (fp16 out) ----------------
__global__ void embed_kernel(const float* __restrict__ x,
                             const float* __restrict__ w_emb,
                             const float* __restrict__ p_emb,
                             const int*   __restrict__ lengths) {
    int bs = blockIdx.x;
    int b = bs / SEQ, s = bs % SEQ;
    __shared__ int s_tok;
    int tid = threadIdx.x;
    if (tid < 32) {
        const float* xp = x + (long long)bs * NVOCAB;
        float bv = -1e30f; int bi = 0;
        for (int c = tid; c < NVOCAB; c += 32) {
            float v = xp[c];
            if (v > bv) { bv = v; bi = c; }
        }
        for (int off = 16; off > 0; off >>= 1) {
            float ov = __shfl_down_sync(0xffffffff, bv, off);
            int   oi = __shfl_down_sync(0xffffffff, bi, off);
            if (ov > bv || (ov == bv && oi < bi)) { bv = ov; bi = oi; }
        }
        if (tid == 0) s_tok = bi;
    }
    __syncthreads();
    int tok = s_tok;
    float valid = (s < lengths[b]) ? 1.0f : 0.0f;
    const float* we = w_emb + (long long)tok * HID;
    const float* pe = p_emb + (long long)s * HID;
    __half* zph = g_z16 + (long long)bs * HID;
    for (int h = tid; h < HID; h += blockDim.x) {
        float v = we[h] * valid + pe[h];
        zph[h] = __float2half(v);
    }
}

// ---------------- residual add + LayerNorm: warp-per-row, no smem, no barriers ----------------
__global__ __launch_bounds__(256)
void add_ln_kernel(const __half* __restrict__ a, const __half* __restrict__ r,
                   const float* __restrict__ sc, const float* __restrict__ bi,
                   __half* __restrict__ out) {
    int warp = threadIdx.x >> 5, lane = threadIdx.x & 31;
    long long row = (long long)blockIdx.x * 8 + warp;
    const __half* ap = a + row * HID;
    const __half* rp = r + row * HID;

    float v[32];
    float s = 0.f, sq = 0.f;
#pragma unroll
    for (int p = 0; p < 4; p++) {
        int h0 = p * 256 + lane * 8;
        uint4 araw = *(const uint4*)(ap + h0);
        uint4 rraw = *(const uint4*)(rp + h0);
        const __half2* a2 = (const __half2*)&araw;
        const __half2* r2 = (const __half2*)&rraw;
#pragma unroll
        for (int j = 0; j < 4; j++) {
            float2 fa = __half22float2(a2[j]);
            float2 fr = __half22float2(r2[j]);
            float v0 = fa.x + fr.x, v1 = fa.y + fr.y;
            v[p * 8 + 2 * j]     = v0;
            v[p * 8 + 2 * j + 1] = v1;
            s  += v0 + v1;
            sq += v0 * v0 + v1 * v1;
        }
    }
#pragma unroll
    for (int off = 16; off > 0; off >>= 1) {
        s  += __shfl_xor_sync(0xffffffff, s,  off);
        sq += __shfl_xor_sync(0xffffffff, sq, off);
    }
    float mean = s * (1.0f / HID);
    float var  = sq * (1.0f / HID) - mean * mean;
    float rstd = rsqrtf(var + 1e-5f);

    __half* op = out + row * HID;
#pragma unroll
    for (int p = 0; p < 4; p++) {
        int h0 = p * 256 + lane * 8;
        float4 sc0 = *(const float4*)(sc + h0);
        float4 sc1 = *(const float4*)(sc + h0 + 4);
        float4 bi0 = *(const float4*)(bi + h0);
        float4 bi1 = *(const float4*)(bi + h0 + 4);
        uint4 oraw;
        __half2* o2 = (__half2*)&oraw;
        o2[0] = __floats2half2_rn((v[p*8+0] - mean) * rstd * sc0.x + bi0.x,
                                  (v[p*8+1] - mean) * rstd * sc0.y + bi0.y);
        o2[1] = __floats2half2_rn((v[p*8+2] - mean) * rstd * sc0.z + bi0.z,
                                  (v[p*8+3] - mean) * rstd * sc0.w + bi0.w);
        o2[2] = __floats2half2_rn((v[p*8+4] - mean) * rstd * sc1.x + bi1.x,
                                  (v[p*8+5] - mean) * rstd * sc1.y + bi1.y);
        o2[3] = __floats2half2_rn((v[p*8+6] - mean) * rstd * sc1.z + bi1.z,
                                  (v[p*8+7] - mean) * rstd * sc1.w + bi1.w);
        *(uint4*)(op + h0) = oraw;
    }
}

// ---------------- mean-pool (half2 vectorized, fp32 accumulate) ----------------
__global__ void pool_kernel() {
    int b = blockIdx.y;
    int h2 = blockIdx.x * 256 + threadIdx.x;     // half2 index, 0..511
    const __half2* zp = (const __half2*)(g_z16 + (long long)b * SEQ * HID) + h2;
    float2 s = make_float2(0.f, 0.f);
#pragma unroll 4
    for (int si = 0; si < SEQ; si++) {
        float2 f = __half22float2(zp[(long long)si * (HID / 2)]);
        s.x += f.x; s.y += f.y;
    }
    g_pool[b * HID + 2 * h2]     = s.x * (1.0f / SEQ);
    g_pool[b * HID + 2 * h2 + 1] = s.y * (1.0f / SEQ);
}

// ---------------- classifier head + softmax(4) ----------------
__global__ void head_kernel(const float* __restrict__ Wfc, const float* __restrict__ bfc,
                            float* __restrict__ out) {
    int b = blockIdx.x;
    int tid = threadIdx.x;
    float p[4] = {0.f, 0.f, 0.f, 0.f};
    const float* zp = g_pool + b * HID;
    for (int h = tid; h < HID; h += 256) {
        float zv = zp[h];
#pragma unroll
        for (int c = 0; c < 4; c++) p[c] += zv * Wfc[h*4 + c];
    }
    __shared__ float red[4][256];
#pragma unroll
    for (int c = 0; c < 4; c++) red[c][tid] = p[c];
    __syncthreads();
    for (int str = 128; str > 0; str >>= 1) {
        if (tid < str)
#pragma unroll
            for (int c = 0; c < 4; c++) red[c][tid] += red[c][tid + str];
        __syncthreads();
    }
    if (tid == 0) {
        float l[4];
        float m = -1e30f;
#pragma unroll
        for (int c = 0; c < 4; c++) { l[c] = red[c][0] + bfc[c]; m = fmaxf(m, l[c]); }
        float ssum = 0.f;
#pragma unroll
        for (int c = 0; c < 4; c++) { l[c] = __expf(l[c] - m); ssum += l[c]; }
        float inv = 1.0f / ssum;
#pragma unroll
        for (int c = 0; c < 4; c++) out[b*4 + c] = l[c] * inv;
    }
}

// ---------------- host orchestration ----------------
extern "C" void kernel_launch(void* const* d_in, const int* in_sizes, int n_in,
                              void* d_out, int out_size) {
    const float* x     = (const float*)d_in[0];
    const float* w_emb = (const float*)d_in[1];
    const float* p_emb = (const float*)d_in[2];
    const float* Wq    = (const float*)d_in[3];
    const float* bq    = (const float*)d_in[4];
    const float* Wk    = (const float*)d_in[5];
    const float* bk    = (const float*)d_in[6];
    const float* Wv    = (const float*)d_in[7];
    const float* bv    = (const float*)d_in[8];
    const float* W1    = (const float*)d_in[9];
    const float* b1    = (const float*)d_in[10];
    const float* W2    = (const float*)d_in[11];
    const float* b2    = (const float*)d_in[12];
    const float* ln1_s = (const float*)d_in[13];
    const float* ln1_b = (const float*)d_in[14];
    const float* ln2_s = (const float*)d_in[15];
    const float* ln2_b = (const float*)d_in[16];
    const float* Wfc   = (const float*)d_in[17];
    const float* bfc   = (const float*)d_in[18];
    const int*   lengths = (const int*)d_in[19];
    float* out = (float*)d_out;

    float *pbqkv;
    __half *pz16, *pz116, *pffh16, *pwqkv16, *pw1216, *pqkv16, *patt16;
    cudaGetSymbolAddress((void**)&pz16,   g_z16);
    cudaGetSymbolAddress((void**)&pz116,  g_z116);
    cudaGetSymbolAddress((void**)&pqkv16, g_qkv16);
    cudaGetSymbolAddress((void**)&patt16, g_att16);
    cudaGetSymbolAddress((void**)&pffh16, g_ffh16);
    cudaGetSymbolAddress((void**)&pwqkv16,g_wqkv16);
    cudaGetSymbolAddress((void**)&pw1216, g_w1216);
    cudaGetSymbolAddress((void**)&pbqkv,  g_bqkv);

    cudaFuncSetAttribute((const void*)gemm_h<0>, cudaFuncAttributeMaxDynamicSharedMemorySize, GEMM_SMEM);
    cudaFuncSetAttribute((const void*)gemm_h<1>, cudaFuncAttributeMaxDynamicSharedMemorySize, GEMM_SMEM);
    cudaFuncSetAttribute((const void*)flash_attn2, cudaFuncAttributeMaxDynamicSharedMemorySize, FA2_SMEM);

    const long long MAT = (long long)HID * HID;

    dim3 tgrid(HID/32, HID/32, 5*NLAYER);     // all 40 matrices, one launch
    dim3 tblk(32, 8);
    transpose_all_kernel<<<tgrid, tblk>>>(Wq, Wk, Wv, W1, W2, pwqkv16, pw1216);
    biaspack_kernel<<<(NLAYER*QKVW + 255)/256, 256>>>(bq, bk, bv);

    embed_kernel<<<BS_TOT, 256>>>(x, w_emb, p_emb, lengths);

    dim3 qkv_grid(QKVW/128, BS_TOT/128);   // (24, 60)
    dim3 ff_grid(HID/128, BS_TOT/128);     // (8, 60)
    dim3 fa_grid(NB*NHEAD, 2);             // (512, 2)

    for (int i = 0; i < NLAYER; i++) {
        long long bOff = (long long)i * HID;
        gemm_h<0><<<qkv_grid, 256, GEMM_SMEM>>>(pz16, pwqkv16 + (long long)i*3*MAT,
                                                pbqkv + (long long)i*QKVW, pqkv16, QKVW);
        flash_attn2<<<fa_grid, 256, FA2_SMEM>>>(pqkv16, lengths, patt16);
        add_ln_kernel<<<BS_TOT/8, 256>>>(patt16, pz16, ln1_s + bOff, ln1_b + bOff, pz116);
        gemm_h<1><<<ff_grid, 256, GEMM_SMEM>>>(pz116, pw1216 + (long long)i*2*MAT,
                                               b1 + bOff, pffh16, HID);
        gemm_h<0><<<ff_grid, 256, GEMM_SMEM>>>(pffh16, pw1216 + (long long)i*2*MAT + MAT,
                                               b2 + bOff, patt16, HID);
        add_ln_kernel<<<BS_TOT/8, 256>>>(patt16, pz116, ln2_s + bOff, ln2_b + bOff, pz16);
    }

    pool_kernel<<<dim3(HID/512, NB), 256>>>();
    head_kernel<<<NB, 256>>>(Wfc, bfc, out);
}

// round 17
// speedup vs baseline: 1.1760x; 1.0337x over previous
#include <cuda_runtime.h>
#include <cuda_fp16.h>
#include <math.h>
#include <cstdint>

#define NB     32
#define SEQ    240
#define HID    1024
#define NLAYER 8
#define NHEAD  16
#define DHEAD  64
#define NVOCAB 48
#define BS_TOT (NB*SEQ)   // 7680
#define QKVW   3072

// ---------------- device scratch (no allocation allowed) ----------------
__device__ __half g_z16 [BS_TOT*HID];      // residual stream (post-LN2 / embed)
__device__ __half g_z116[BS_TOT*HID];      // post-LN1
__device__ __half g_qkv16[(long long)BS_TOT*QKVW];
__device__ __half g_att16[BS_TOT*HID];     // attention out & FFN out (fp16)
__device__ __half g_ffh16[BS_TOT*HID];
__device__ float  g_pool[NB*HID];
__device__ __half g_wqkv16[(long long)NLAYER*3*HID*HID];  // [L][3072][1024] transposed fp16
__device__ __half g_w1216 [(long long)NLAYER*2*HID*HID];  // [L][W1t|W2t] fp16
__device__ float  g_bqkv[NLAYER*QKVW];

// ============================ helpers ============================
__device__ __forceinline__ uint32_t smem_u32(const void* p) {
    return (uint32_t)__cvta_generic_to_shared(p);
}
__device__ __forceinline__ void cpa16(uint32_t dst, const void* src) {
    asm volatile("cp.async.cg.shared.global [%0], [%1], 16;" :: "r"(dst), "l"(src));
}
#define CPA_COMMIT() asm volatile("cp.async.commit_group;" ::: "memory")
template<int N> __device__ __forceinline__ void cpa_wait() {
    asm volatile("cp.async.wait_group %0;" :: "n"(N) : "memory");
}

__device__ __forceinline__ void mma_f16(float* c, const uint32_t* a, uint32_t b0, uint32_t b1) {
    asm volatile(
        "mma.sync.aligned.m16n8k16.row.col.f32.f16.f16.f32 "
        "{%0,%1,%2,%3}, {%4,%5,%6,%7}, {%8,%9}, {%0,%1,%2,%3};"
        : "+f"(c[0]), "+f"(c[1]), "+f"(c[2]), "+f"(c[3])
        : "r"(a[0]), "r"(a[1]), "r"(a[2]), "r"(a[3]), "r"(b0), "r"(b1));
}
__device__ __forceinline__ void ldsm_x4(uint32_t* r, uint32_t addr) {
    asm volatile("ldmatrix.sync.aligned.m8n8.x4.shared.b16 {%0,%1,%2,%3}, [%4];"
        : "=r"(r[0]), "=r"(r[1]), "=r"(r[2]), "=r"(r[3]) : "r"(addr));
}
__device__ __forceinline__ void ldsm_x4_t(uint32_t* r, uint32_t addr) {
    asm volatile("ldmatrix.sync.aligned.m8n8.x4.trans.shared.b16 {%0,%1,%2,%3}, [%4];"
        : "=r"(r[0]), "=r"(r[1]), "=r"(r[2]), "=r"(r[3]) : "r"(addr));
}

// ============================ merged weight transpose -> fp16 ============================
__global__ void transpose_all_kernel(const float* __restrict__ Wq, const float* __restrict__ Wk,
                                     const float* __restrict__ Wv, const float* __restrict__ W1,
                                     const float* __restrict__ W2,
                                     __half* __restrict__ wqkv, __half* __restrict__ w12) {
    __shared__ float t[32][33];
    const long long MAT = (long long)HID * HID;
    int z = blockIdx.z;
    int ty_ = z / NLAYER;            // 0..4
    int l  = z % NLAYER;
    const float* src =
        (ty_ == 0 ? Wq : ty_ == 1 ? Wk : ty_ == 2 ? Wv : ty_ == 3 ? W1 : W2) + (long long)l * MAT;
    __half* dst = (ty_ < 3) ? (wqkv + (long long)l * 3 * MAT + (long long)ty_ * MAT)
                            : (w12  + (long long)l * 2 * MAT + (long long)(ty_ - 3) * MAT);
    int x0 = blockIdx.x * 32, y0 = blockIdx.y * 32;
    int tx = threadIdx.x, ty = threadIdx.y;  // 32 x 8
#pragma unroll
    for (int j = 0; j < 32; j += 8)
        t[ty + j][tx] = src[(long long)(y0 + ty + j) * HID + x0 + tx];
    __syncthreads();
#pragma unroll
    for (int j = 0; j < 32; j += 8)
        dst[(long long)(x0 + ty + j) * HID + y0 + tx] = __float2half(t[tx][ty + j]);
}

// bias pack: g_bqkv[l][t*1024+n]
__global__ void biaspack_kernel(const float* __restrict__ bq, const float* __restrict__ bk,
                                const float* __restrict__ bv) {
    int idx = blockIdx.x * 256 + threadIdx.x;
    if (idx >= NLAYER * QKVW) return;
    int l = idx / QKVW, r = idx % QKVW;
    int t = r >> 10, n = r & 1023;
    const float* src = (t == 0) ? bq : (t == 1) ? bk : bv;
    g_bqkv[idx] = src[l * HID + n];
}

// ============================ fp16 mma.sync GEMM (BK=64 probe) ============================
// C[M,N] = A[M,K] @ Wt^T + bias ; A fp16 [M,K] (lda=HID), Wt fp16 [N,K].
// BM=128, BN=128, BK=64 halves; 256 threads; warp grid 4x2, warp tile 32x64; 2 CTA/SM.
// Same load-issue -> wait -> sync loop skeleton as R12 (proven); fewer, longer iterations.
#define BKC   64
#define PADH  72                          // halves per smem row (144B); rows hit 4r%32 banks
#define ABYTES (128 * PADH * 2)           // 18432
#define STAGEB (2 * ABYTES)               // 36864
#define NSTAGE 3
#define GEMM_SMEM (NSTAGE * STAGEB)       // 110592 (x2 CTA = 221KB <= 228KB/SM)

__device__ __forceinline__ void gemm_load_stage(uint32_t sbase, int s, int kc, int tid,
                                                const __half* __restrict__ A,
                                                const __half* __restrict__ Bw,
                                                int row0, int col0) {
    uint32_t abase = sbase + s * STAGEB;
    uint32_t bbase = abase + ABYTES;
    const __half* Ag = A  + (long long)row0 * HID + kc * BKC;
    const __half* Bg = Bw + (long long)col0 * HID + kc * BKC;
#pragma unroll
    for (int j = 0; j < 4; j++) {
        int c = tid + j * 256;            // 0..1023
        int r = c >> 3, q = c & 7;        // row 0..127, 16B-chunk 0..7
        uint32_t so = (uint32_t)(r * PADH + q * 8) * 2;
        cpa16(abase + so, Ag + (long long)r * HID + q * 8);
        cpa16(bbase + so, Bg + (long long)r * HID + q * 8);
    }
}

// ACT: GELU on output (output always fp16)
template<int ACT>
__global__ __launch_bounds__(256, 2)
void gemm_h(const __half* __restrict__ A, const __half* __restrict__ Bw,
            const float* __restrict__ bias, __half* __restrict__ C, int ldC) {
    extern __shared__ __half smem[];
    const int tid = threadIdx.x;
    const int wid = tid >> 5, lane = tid & 31;
    const int wm = wid & 3, wn = wid >> 2;
    const int grp = lane >> 2, qid = lane & 3;
    const int row0 = blockIdx.y * 128;
    const int col0 = blockIdx.x * 128;
    uint32_t sbase = smem_u32(smem);

    float acc[2][8][4];
#pragma unroll
    for (int mf = 0; mf < 2; mf++)
#pragma unroll
        for (int nf = 0; nf < 8; nf++)
#pragma unroll
            for (int i = 0; i < 4; i++) acc[mf][nf][i] = 0.f;

    const int NKC = HID / BKC;   // 16

    gemm_load_stage(sbase, 0, 0, tid, A, Bw, row0, col0);
    CPA_COMMIT();
    gemm_load_stage(sbase, 1, 1, tid, A, Bw, row0, col0);
    CPA_COMMIT();

    const int a_row = wm * 32 + (lane & 15);
    const int a_k   = (lane >> 4) * 8;       // 0 or 8 within each 16-k chunk
    const int b_row = wn * 64 + (lane & 7);
    const int b_k   = (lane >> 3) * 8;       // 0..24, covers 32 halves per ldsm.x4

    for (int kc = 0; kc < NKC; kc++) {
        int s = kc % NSTAGE;
        if (kc + 2 < NKC)
            gemm_load_stage(sbase, (kc + 2) % NSTAGE, kc + 2, tid, A, Bw, row0, col0);
        CPA_COMMIT();
        cpa_wait<2>();
        __syncthreads();

        uint32_t sAu = sbase + s * STAGEB;
        uint32_t sBu = sAu + ABYTES;

        // A fragments: 4 k16-chunks x 2 m-frags
        uint32_t afr[2][4][4];
#pragma unroll
        for (int mf = 0; mf < 2; mf++)
#pragma unroll
            for (int kk = 0; kk < 4; kk++)
                ldsm_x4(afr[mf][kk],
                        sAu + (uint32_t)((a_row + mf * 16) * PADH + kk * 16 + a_k) * 2);

#pragma unroll
        for (int nf = 0; nf < 8; nf++) {
            uint32_t b0[4], b1[4];
            uint32_t brow = (uint32_t)((b_row + nf * 8) * PADH);
            ldsm_x4(b0, sBu + (brow + b_k) * 2);         // k 0..31
            ldsm_x4(b1, sBu + (brow + 32 + b_k) * 2);    // k 32..63
            mma_f16(acc[0][nf], afr[0][0], b0[0], b0[1]);
            mma_f16(acc[1][nf], afr[1][0], b0[0], b0[1]);
            mma_f16(acc[0][nf], afr[0][1], b0[2], b0[3]);
            mma_f16(acc[1][nf], afr[1][1], b0[2], b0[3]);
            mma_f16(acc[0][nf], afr[0][2], b1[0], b1[1]);
            mma_f16(acc[1][nf], afr[1][2], b1[0], b1[1]);
            mma_f16(acc[0][nf], afr[0][3], b1[2], b1[3]);
            mma_f16(acc[1][nf], afr[1][3], b1[2], b1[3]);
        }
        __syncthreads();
    }

#pragma unroll
    for (int mf = 0; mf < 2; mf++) {
        int r0 = row0 + wm * 32 + mf * 16 + grp;
#pragma unroll
        for (int nf = 0; nf < 8; nf++) {
            int cg = col0 + wn * 64 + nf * 8 + 2 * qid;
            float bv0 = bias[cg], bv1 = bias[cg + 1];
            float v00 = acc[mf][nf][0] + bv0;
            float v01 = acc[mf][nf][1] + bv1;
            float v10 = acc[mf][nf][2] + bv0;
            float v11 = acc[mf][nf][3] + bv1;
            if (ACT) {
                v00 = 0.5f * v00 * (1.0f + erff(v00 * 0.70710678118654752f));
                v01 = 0.5f * v01 * (1.0f + erff(v01 * 0.70710678118654752f));
                v10 = 0.5f * v10 * (1.0f + erff(v10 * 0.70710678118654752f));
                v11 = 0.5f * v11 * (1.0f + erff(v11 * 0.70710678118654752f));
            }
            *(__half2*)&C[(long long)r0 * ldC + cg]       = __floats2half2_rn(v00, v01);
            *(__half2*)&C[(long long)(r0 + 8) * ldC + cg] = __floats2half2_rn(v10, v11);
        }
    }
}

// ============================ tensor-core flash attention (flash-v2) ============================
#define PADH2   72
#define QH_OFF  0
#define KH_OFF  (128 * PADH2 * 2)           // 18432
#define VH_OFF  (KH_OFF + 240 * PADH2 * 2)  // 52992
#define FA2_SMEM (VH_OFF + 240 * PADH2 * 2) // 87552

__global__ __launch_bounds__(256, 2)
void flash_attn2(const __half* __restrict__ qkv, const int* __restrict__ lengths,
                 __half* __restrict__ att) {
    extern __shared__ char fsm[];
    const int bh = blockIdx.x;
    const int half = blockIdx.y;
    const int b = bh >> 4, h = bh & 15;
    const int tid = threadIdx.x;
    const int w = tid >> 5, lane = tid & 31;
    const int grp = lane >> 2, qid = lane & 3;
    const int rbase = half * 128;
    const int len = lengths[b];
    const int kneed = half ? 240 : 128;

    const __half* base = qkv + (long long)b * SEQ * QKVW + h * DHEAD;

    {
        const int nQ = 128 * 8, nK = kneed * 8;
        for (int i = tid; i < nQ + 2 * nK; i += 256) {
            uint4 val = make_uint4(0, 0, 0, 0);
            char* dst;
            if (i < nQ) {
                int r = i >> 3, c = i & 7;
                int s = rbase + r;
                if (s < SEQ) val = *(const uint4*)(base + (long long)s * QKVW + c * 8);
                dst = fsm + QH_OFF + (r * PADH2 + c * 8) * 2;
            } else if (i < nQ + nK) {
                int j = i - nQ; int r = j >> 3, c = j & 7;
                val = *(const uint4*)(base + (long long)r * QKVW + 1024 + c * 8);
                dst = fsm + KH_OFF + (r * PADH2 + c * 8) * 2;
            } else {
                int j = i - nQ - nK; int r = j >> 3, c = j & 7;
                val = *(const uint4*)(base + (long long)r * QKVW + 2048 + c * 8);
                dst = fsm + VH_OFF + (r * PADH2 + c * 8) * 2;
            }
            *(uint4*)dst = val;
        }
    }
    __syncthreads();

    if (rbase + w * 16 >= SEQ) return;

    const uint32_t sb = smem_u32(fsm);
    const uint32_t QhU = sb + QH_OFF, KhU = sb + KH_OFF, VhU = sb + VH_OFF;

    const int row0g = rbase + w * 16 + grp;
    const int row1g = row0g + 8;
    const int nch = min(8 * half + w + 1, 15);

    uint32_t qf[4][4];
#pragma unroll
    for (int dk = 0; dk < 4; dk++)
        ldsm_x4(qf[dk], QhU + (uint32_t)((w * 16 + (lane & 15)) * PADH2
                                         + dk * 16 + ((lane >> 4) << 3)) * 2);

    float m0 = -1e30f, m1 = -1e30f, l0 = 0.f, l1 = 0.f;
    float acc[8][4];
#pragma unroll
    for (int nf = 0; nf < 8; nf++)
#pragma unroll
        for (int i = 0; i < 4; i++) acc[nf][i] = 0.f;

    const float sc = 1.0f / 32.0f;

    for (int kc = 0; kc < nch; kc++) {
        float S[2][4];
#pragma unroll
        for (int ng = 0; ng < 2; ng++)
#pragma unroll
            for (int i = 0; i < 4; i++) S[ng][i] = 0.f;

#pragma unroll
        for (int dg2 = 0; dg2 < 2; dg2++) {
#pragma unroll
            for (int ng = 0; ng < 2; ng++) {
                uint32_t kb[4];
                ldsm_x4(kb, KhU + (uint32_t)((kc * 16 + ng * 8 + (lane & 7)) * PADH2
                                             + dg2 * 32 + ((lane >> 3) << 3)) * 2);
                mma_f16(S[ng], qf[dg2 * 2 + 0], kb[0], kb[1]);
                mma_f16(S[ng], qf[dg2 * 2 + 1], kb[2], kb[3]);
            }
        }

        float s_[2][4];
#pragma unroll
        for (int ng = 0; ng < 2; ng++) {
            int colb = kc * 16 + ng * 8 + 2 * qid;
            s_[ng][0] = (colb     <= row0g) ? S[ng][0] * sc : -1e30f;
            s_[ng][1] = (colb + 1 <= row0g) ? S[ng][1] * sc : -1e30f;
            s_[ng][2] = (colb     <= row1g) ? S[ng][2] * sc : -1e30f;
            s_[ng][3] = (colb + 1 <= row1g) ? S[ng][3] * sc : -1e30f;
        }

        float mc0 = fmaxf(fmaxf(s_[0][0], s_[0][1]), fmaxf(s_[1][0], s_[1][1]));
        float mc1 = fmaxf(fmaxf(s_[0][2], s_[0][3]), fmaxf(s_[1][2], s_[1][3]));
        mc0 = fmaxf(mc0, __shfl_xor_sync(0xffffffff, mc0, 1));
        mc0 = fmaxf(mc0, __shfl_xor_sync(0xffffffff, mc0, 2));
        mc1 = fmaxf(mc1, __shfl_xor_sync(0xffffffff, mc1, 1));
        mc1 = fmaxf(mc1, __shfl_xor_sync(0xffffffff, mc1, 2));
        float m0n = fmaxf(m0, mc0), m1n = fmaxf(m1, mc1);
        float sf0 = __expf(m0 - m0n), sf1 = __expf(m1 - m1n);

        float p[2][4];
#pragma unroll
        for (int ng = 0; ng < 2; ng++) {
            p[ng][0] = __expf(s_[ng][0] - m0n);
            p[ng][1] = __expf(s_[ng][1] - m0n);
            p[ng][2] = __expf(s_[ng][2] - m1n);
            p[ng][3] = __expf(s_[ng][3] - m1n);
        }
        float rs0 = p[0][0] + p[0][1] + p[1][0] + p[1][1];
        float rs1 = p[0][2] + p[0][3] + p[1][2] + p[1][3];
        rs0 += __shfl_xor_sync(0xffffffff, rs0, 1);
        rs0 += __shfl_xor_sync(0xffffffff, rs0, 2);
        rs1 += __shfl_xor_sync(0xffffffff, rs1, 1);
        rs1 += __shfl_xor_sync(0xffffffff, rs1, 2);
        l0 = l0 * sf0 + rs0;  m0 = m0n;
        l1 = l1 * sf1 + rs1;  m1 = m1n;

#pragma unroll
        for (int nf = 0; nf < 8; nf++) {
            acc[nf][0] *= sf0; acc[nf][1] *= sf0;
            acc[nf][2] *= sf1; acc[nf][3] *= sf1;
        }

        uint32_t ap[4];
        {
            __half2 h0 = __floats2half2_rn(p[0][0], p[0][1]);
            __half2 h1 = __floats2half2_rn(p[0][2], p[0][3]);
            __half2 h2 = __floats2half2_rn(p[1][0], p[1][1]);
            __half2 h3 = __floats2half2_rn(p[1][2], p[1][3]);
            ap[0] = *(uint32_t*)&h0;
            ap[1] = *(uint32_t*)&h1;
            ap[2] = *(uint32_t*)&h2;
            ap[3] = *(uint32_t*)&h3;
        }

#pragma unroll
        for (int dg = 0; dg < 4; dg++) {
            uint32_t vb[4];
            ldsm_x4_t(vb, VhU + (uint32_t)((kc * 16 + (lane & 15)) * PADH2
                                           + dg * 16 + ((lane >> 4) << 3)) * 2);
            mma_f16(acc[2 * dg],     ap, vb[0], vb[1]);
            mma_f16(acc[2 * dg + 1], ap, vb[2], vb[3]);
        }
    }

    float inv0 = (row0g < len) ? (1.0f / l0) : 0.0f;
    float inv1 = (row1g < len) ? (1.0f / l1) : 0.0f;
    __half* ob0 = att + (long long)(b * SEQ + row0g) * HID + h * DHEAD;
    __half* ob1 = att + (long long)(b * SEQ + row1g) * HID + h * DHEAD;
#pragma unroll
    for (int nf = 0; nf < 8; nf++) {
        int col = (nf >> 1) * 16 + (nf & 1) * 8 + 2 * qid;
        *(__half2*)&ob0[col] = __floats2half2_rn(acc[nf][0] * inv0, acc[nf][1] * inv0);
        *(__half2*)&ob1[col] = __floats2half2_rn(acc[nf][2] * inv1, acc[nf][3] * inv1);
    }
}

// ---------------- embedding: argmax + gather + posenc (fp16 out) ----------------
__global__ void embed_kernel(const float* __restrict__ x,
                             const float* __restrict__ w_emb,
                             const float* __restrict__ p_emb,
                             const int*   __restrict__ lengths) {
    int bs = blockIdx.x;
    int b = bs / SEQ, s = bs % SEQ;
    __shared__ int s_tok;
    int tid = threadIdx.x;
    if (tid < 32) {
        const float* xp = x + (long long)bs * NVOCAB;
        float bv = -1e30f; int bi = 0;
        for (int c = tid; c < NVOCAB; c += 32) {
            float v = xp[c];
            if (v > bv) { bv = v; bi = c; }
        }
        for (int off = 16; off > 0; off >>= 1) {
            float ov = __shfl_down_sync(0xffffffff, bv, off);
            int   oi = __shfl_down_sync(0xffffffff, bi, off);
            if (ov > bv || (ov == bv && oi < bi)) { bv = ov; bi = oi; }
        }
        if (tid == 0) s_tok = bi;
    }
    __syncthreads();
    int tok = s_tok;
    float valid = (s < lengths[b]) ? 1.0f : 0.0f;
    const float* we = w_emb + (long long)tok * HID;
    const float* pe = p_emb + (long long)s * HID;
    __half* zph = g_z16 + (long long)bs * HID;
    for (int h = tid; h < HID; h += blockDim.x) {
        float v = we[h] * valid + pe[h];
        zph[h] = __float2half(v);
    }
}

// ---------------- residual add + LayerNorm: warp-per-row, no smem, no barriers ----------------
__global__ __launch_bounds__(256)
void add_ln_kernel(const __half* __restrict__ a, const __half* __restrict__ r,
                   const float* __restrict__ sc, const float* __restrict__ bi,
                   __half* __restrict__ out) {
    int warp = threadIdx.x >> 5, lane = threadIdx.x & 31;
    long long row = (long long)blockIdx.x * 8 + warp;
    const __half* ap = a + row * HID;
    const __half* rp = r + row * HID;

    float v[32];
    float s = 0.f, sq = 0.f;
#pragma unroll
    for (int p = 0; p < 4; p++) {
        int h0 = p * 256 + lane * 8;
        uint4 araw = *(const uint4*)(ap + h0);
        uint4 rraw = *(const uint4*)(rp + h0);
        const __half2* a2 = (const __half2*)&araw;
        const __half2* r2 = (const __half2*)&rraw;
#pragma unroll
        for (int j = 0; j < 4; j++) {
            float2 fa = __half22float2(a2[j]);
            float2 fr = __half22float2(r2[j]);
            float v0 = fa.x + fr.x, v1 = fa.y + fr.y;
            v[p * 8 + 2 * j]     = v0;
            v[p * 8 + 2 * j + 1] = v1;
            s  += v0 + v1;
            sq += v0 * v0 + v1 * v1;
        }
    }
#pragma unroll
    for (int off = 16; off > 0; off >>= 1) {
        s  += __shfl_xor_sync(0xffffffff, s,  off);
        sq += __shfl_xor_sync(0xffffffff, sq, off);
    }
    float mean = s * (1.0f / HID);
    float var  = sq * (1.0f / HID) - mean * mean;
    float rstd = rsqrtf(var + 1e-5f);

    __half* op = out + row * HID;
#pragma unroll
    for (int p = 0; p < 4; p++) {
        int h0 = p * 256 + lane * 8;
        float4 sc0 = *(const float4*)(sc + h0);
        float4 sc1 = *(const float4*)(sc + h0 + 4);
        float4 bi0 = *(const float4*)(bi + h0);
        float4 bi1 = *(const float4*)(bi + h0 + 4);
        uint4 oraw;
        __half2* o2 = (__half2*)&oraw;
        o2[0] = __floats2half2_rn((v[p*8+0] - mean) * rstd * sc0.x + bi0.x,
                                  (v[p*8+1] - mean) * rstd * sc0.y + bi0.y);
        o2[1] = __floats2half2_rn((v[p*8+2] - mean) * rstd * sc0.z + bi0.z,
                                  (v[p*8+3] - mean) * rstd * sc0.w + bi0.w);
        o2[2] = __floats2half2_rn((v[p*8+4] - mean) * rstd * sc1.x + bi1.x,
                                  (v[p*8+5] - mean) * rstd * sc1.y + bi1.y);
        o2[3] = __floats2half2_rn((v[p*8+6] - mean) * rstd * sc1.z + bi1.z,
                                  (v[p*8+7] - mean) * rstd * sc1.w + bi1.w);
        *(uint4*)(op + h0) = oraw;
    }
}

// ---------------- mean-pool (half2 vectorized, fp32 accumulate) ----------------
__global__ void pool_kernel() {
    int b = blockIdx.y;
    int h2 = blockIdx.x * 256 + threadIdx.x;     // half2 index, 0..511
    const __half2* zp = (const __half2*)(g_z16 + (long long)b * SEQ * HID) + h2;
    float2 s = make_float2(0.f, 0.f);
#pragma unroll 4
    for (int si = 0; si < SEQ; si++) {
        float2 f = __half22float2(zp[(long long)si * (HID / 2)]);
        s.x += f.x; s.y += f.y;
    }
    g_pool[b * HID + 2 * h2]     = s.x * (1.0f / SEQ);
    g_pool[b * HID + 2 * h2 + 1] = s.y * (1.0f / SEQ);
}

// ---------------- classifier head + softmax(4) ----------------
__global__ void head_kernel(const float* __restrict__ Wfc, const float* __restrict__ bfc,
                            float* __restrict__ out) {
    int b = blockIdx.x;
    int tid = threadIdx.x;
    float p[4] = {0.f, 0.f, 0.f, 0.f};
    const float* zp = g_pool + b * HID;
    for (int h = tid; h < HID; h += 256) {
        float zv = zp[h];
#pragma unroll
        for (int c = 0; c < 4; c++) p[c] += zv * Wfc[h*4 + c];
    }
    __shared__ float red[4][256];
#pragma unroll
    for (int c = 0; c < 4; c++) red[c][tid] = p[c];
    __syncthreads();
    for (int str = 128; str > 0; str >>= 1) {
        if (tid < str)
#pragma unroll
            for (int c = 0; c < 4; c++) red[c][tid] += red[c][tid + str];
        __syncthreads();
    }
    if (tid == 0) {
        float l[4];
        float m = -1e30f;
#pragma unroll
        for (int c = 0; c < 4; c++) { l[c] = red[c][0] + bfc[c]; m = fmaxf(m, l[c]); }
        float ssum = 0.f;
#pragma unroll
        for (int c = 0; c < 4; c++) { l[c] = __expf(l[c] - m); ssum += l[c]; }
        float inv = 1.0f / ssum;
#pragma unroll
        for (int c = 0; c < 4; c++) out[b*4 + c] = l[c] * inv;
    }
}

// ---------------- host orchestration ----------------
extern "C" void kernel_launch(void* const* d_in, const int* in_sizes, int n_in,
                              void* d_out, int out_size) {
    const float* x     = (const float*)d_in[0];
    const float* w_emb = (const float*)d_in[1];
    const float* p_emb = (const float*)d_in[2];
    const float* Wq    = (const float*)d_in[3];
    const float* bq    = (const float*)d_in[4];
    const float* Wk    = (const float*)d_in[5];
    const float* bk    = (const float*)d_in[6];
    const float* Wv    = (const float*)d_in[7];
    const float* bv    = (const float*)d_in[8];
    const float* W1    = (const float*)d_in[9];
    const float* b1    = (const float*)d_in[10];
    const float* W2    = (const float*)d_in[11];
    const float* b2    = (const float*)d_in[12];
    const float* ln1_s = (const float*)d_in[13];
    const float* ln1_b = (const float*)d_in[14];
    const float* ln2_s = (const float*)d_in[15];
    const float* ln2_b = (const float*)d_in[16];
    const float* Wfc   = (const float*)d_in[17];
    const float* bfc   = (const float*)d_in[18];
    const int*   lengths = (const int*)d_in[19];
    float* out = (float*)d_out;

    float *pbqkv;
    __half *pz16, *pz116, *pffh16, *pwqkv16, *pw1216, *pqkv16, *patt16;
    cudaGetSymbolAddress((void**)&pz16,   g_z16);
    cudaGetSymbolAddress((void**)&pz116,  g_z116);
    cudaGetSymbolAddress((void**)&pqkv16, g_qkv16);
    cudaGetSymbolAddress((void**)&patt16, g_att16);
    cudaGetSymbolAddress((void**)&pffh16, g_ffh16);
    cudaGetSymbolAddress((void**)&pwqkv16,g_wqkv16);
    cudaGetSymbolAddress((void**)&pw1216, g_w1216);
    cudaGetSymbolAddress((void**)&pbqkv,  g_bqkv);

    cudaFuncSetAttribute((const void*)gemm_h<0>, cudaFuncAttributeMaxDynamicSharedMemorySize, GEMM_SMEM);
    cudaFuncSetAttribute((const void*)gemm_h<1>, cudaFuncAttributeMaxDynamicSharedMemorySize, GEMM_SMEM);
    cudaFuncSetAttribute((const void*)flash_attn2, cudaFuncAttributeMaxDynamicSharedMemorySize, FA2_SMEM);

    const long long MAT = (long long)HID * HID;

    dim3 tgrid(HID/32, HID/32, 5*NLAYER);     // all 40 matrices, one launch
    dim3 tblk(32, 8);
    transpose_all_kernel<<<tgrid, tblk>>>(Wq, Wk, Wv, W1, W2, pwqkv16, pw1216);
    biaspack_kernel<<<(NLAYER*QKVW + 255)/256, 256>>>(bq, bk, bv);

    embed_kernel<<<BS_TOT, 256>>>(x, w_emb, p_emb, lengths);

    dim3 qkv_grid(QKVW/128, BS_TOT/128);   // (24, 60)
    dim3 ff_grid(HID/128, BS_TOT/128);     // (8, 60)
    dim3 fa_grid(NB*NHEAD, 2);             // (512, 2)

    for (int i = 0; i < NLAYER; i++) {
        long long bOff = (long long)i * HID;
        gemm_h<0><<<qkv_grid, 256, GEMM_SMEM>>>(pz16, pwqkv16 + (long long)i*3*MAT,
                                                pbqkv + (long long)i*QKVW, pqkv16, QKVW);
        flash_attn2<<<fa_grid, 256, FA2_SMEM>>>(pqkv16, lengths, patt16);
        add_ln_kernel<<<BS_TOT/8, 256>>>(patt16, pz16, ln1_s + bOff, ln1_b + bOff, pz116);
        gemm_h<1><<<ff_grid, 256, GEMM_SMEM>>>(pz116, pw1216 + (long long)i*2*MAT,
                                               b1 + bOff, pffh16, HID);
        gemm_h<0><<<ff_grid, 256, GEMM_SMEM>>>(pffh16, pw1216 + (long long)i*2*MAT + MAT,
                                               b2 + bOff, patt16, HID);
        add_ln_kernel<<<BS_TOT/8, 256>>>(patt16, pz116, ln2_s + bOff, ln2_b + bOff, pz16);
    }

    pool_kernel<<<dim3(HID/512, NB), 256>>>();
    head_kernel<<<NB, 256>>>(Wfc, bfc, out);
}